// round 2
// baseline (speedup 1.0000x reference)
#include <cuda_runtime.h>
#include <cuda_bf16.h>

#define BB 32
#define LL 512
#define EE 512
#define HH 1024
#define VV 32000
#define TT 64
#define G4H 4096

// ---------------- scratch (device globals; no allocation allowed) ----------------
__device__ float g_enc_proj[BB * LL * HH];   // 67 MB
__device__ float g_h[2 * BB * HH];
__device__ float g_c[2 * BB * HH];
__device__ float g_q[BB * HH];
__device__ float g_e[BB * LL];
__device__ float g_alpha[BB * LL];
__device__ float g_ctxp[8 * BB * HH];
__device__ float g_ctx[BB * HH];
__device__ float g_x[BB * EE];
__device__ float g_gp0[BB * G4H];
__device__ float g_gp1[BB * G4H];
__device__ int   g_tok[BB];

__device__ __forceinline__ float acc_sig(float x) {
    return 1.0f / (1.0f + expf(-x));
}

// ---------------- init ----------------
__global__ void init_kernel(const int* __restrict__ trg, float* __restrict__ out) {
    int gid = blockIdx.x * blockDim.x + threadIdx.x;
    // zero outputs[:, 0, :]
    if (gid < BB * VV) {
        int b = gid / VV, v = gid - b * VV;
        out[(long long)b * TT * VV + v] = 0.0f;
    }
    if (gid < 2 * BB * HH) { g_h[gid] = 0.0f; g_c[gid] = 0.0f; }
    if (gid < BB) {
        g_tok[gid] = trg[gid * TT];                            // trg[:,0] (int32!)
        out[(long long)BB * TT * VV + gid * TT] = 1.0f;        // _pred[:,0] = sos
    }
}

// ---------------- generic M=32 x N GEMM: out[b,n] = bias[n] + sum_k act[b,k]*W[n,k] --------
// actSel: 0=ptr 1=g_x 2=g_h(layer0) 3=g_h(layer1)
// outSel: 0=ptr 1=g_enc_proj 2=g_gp0 3=g_gp1
__device__ __forceinline__ const float* pick_act(int sel, const float* p) {
    if (sel == 1) return g_x;
    if (sel == 2) return g_h;
    if (sel == 3) return g_h + BB * HH;
    return p;
}
__device__ __forceinline__ float* pick_out(int sel, float* p) {
    if (sel == 1) return g_enc_proj;
    if (sel == 2) return g_gp0;
    if (sel == 3) return g_gp1;
    return p;
}

__global__ __launch_bounds__(128) void gemm_m32(
    const float* __restrict__ W, int actSel, const float* __restrict__ actPtr,
    const float* __restrict__ bias, int outSel, float* __restrict__ outPtr,
    int N, int K, long long outStride)
{
    __shared__ __align__(16) float As[16][36];
    __shared__ __align__(16) float Ws[16][68];

    const int n0 = blockIdx.x * 64;
    const float* act = pick_act(actSel, actPtr) + (long long)blockIdx.y * 32 * K;
    float* out = pick_out(outSel, outPtr) + (long long)blockIdx.y * 32 * outStride;

    const int tid = threadIdx.x;
    const int a_b = tid & 31, a_kq = tid >> 5;          // act load: 32b x 4 k-quads
    const int w_n = tid & 63, w_kq = tid >> 6;          // W load: 64n x 2 k-octs
    const int c_nq = tid & 15, c_bq = tid >> 4;         // compute: 16 n-quads x 8 b-quads

    float acc[4][4];
#pragma unroll
    for (int i = 0; i < 4; i++)
#pragma unroll
        for (int j = 0; j < 4; j++) acc[i][j] = 0.0f;

    for (int k0 = 0; k0 < K; k0 += 16) {
        float4 av = *(const float4*)(act + (long long)a_b * K + k0 + a_kq * 4);
        float4 wv0 = *(const float4*)(W + (long long)(n0 + w_n) * K + k0 + w_kq * 8);
        float4 wv1 = *(const float4*)(W + (long long)(n0 + w_n) * K + k0 + w_kq * 8 + 4);
        __syncthreads();
        As[a_kq * 4 + 0][a_b] = av.x;
        As[a_kq * 4 + 1][a_b] = av.y;
        As[a_kq * 4 + 2][a_b] = av.z;
        As[a_kq * 4 + 3][a_b] = av.w;
        Ws[w_kq * 8 + 0][w_n] = wv0.x;
        Ws[w_kq * 8 + 1][w_n] = wv0.y;
        Ws[w_kq * 8 + 2][w_n] = wv0.z;
        Ws[w_kq * 8 + 3][w_n] = wv0.w;
        Ws[w_kq * 8 + 4][w_n] = wv1.x;
        Ws[w_kq * 8 + 5][w_n] = wv1.y;
        Ws[w_kq * 8 + 6][w_n] = wv1.z;
        Ws[w_kq * 8 + 7][w_n] = wv1.w;
        __syncthreads();
#pragma unroll
        for (int k = 0; k < 16; k++) {
            float4 a = *(const float4*)&As[k][c_bq * 4];
            float4 w = *(const float4*)&Ws[k][c_nq * 4];
            float ar[4] = {a.x, a.y, a.z, a.w};
            float wr[4] = {w.x, w.y, w.z, w.w};
#pragma unroll
            for (int i = 0; i < 4; i++)
#pragma unroll
                for (int j = 0; j < 4; j++) acc[i][j] += ar[i] * wr[j];
        }
    }
#pragma unroll
    for (int i = 0; i < 4; i++) {
        int b = c_bq * 4 + i;
#pragma unroll
        for (int j = 0; j < 4; j++) {
            int n = n0 + c_nq * 4 + j;
            float bv = bias ? bias[n] : 0.0f;
            out[(long long)b * outStride + n] = acc[i][j] + bv;
        }
    }
}

// ---------------- q = h1 @ W_att_dec^T + b  (warp per (b,n)) ----------------
__global__ void q_kernel(const float* __restrict__ Wd, const float* __restrict__ bd) {
    int gw = blockIdx.x * 8 + (threadIdx.x >> 5);
    int lane = threadIdx.x & 31;
    int n = gw & (HH - 1), b = gw >> 10;
    const float* w = Wd + (long long)n * HH;
    const float* a = g_h + BB * HH + b * HH;   // h1
    float s = 0.0f;
#pragma unroll
    for (int it = 0; it < 8; it++) {
        int k = it * 128 + lane * 4;
        float4 wv = *(const float4*)(w + k);
        float4 av = *(const float4*)(a + k);
        s += wv.x * av.x + wv.y * av.y + wv.z * av.z + wv.w * av.w;
    }
#pragma unroll
    for (int o = 16; o; o >>= 1) s += __shfl_xor_sync(0xffffffffu, s, o);
    if (!lane) g_q[b * HH + n] = s + bd[n];
}

// ---------------- energy: e[b,l] = sum_h tanh(enc_proj + q) * v_att ----------------
__global__ void energy_kernel(const float* __restrict__ v_att) {
    __shared__ float qs[HH];
    __shared__ float vs[HH];
    int b = blockIdx.x >> 6;
    int l0 = (blockIdx.x & 63) << 3;
    {
        int i = threadIdx.x * 4;
        *(float4*)&qs[i] = *(const float4*)&g_q[b * HH + i];
        *(float4*)&vs[i] = *(const float4*)&v_att[i];
    }
    __syncthreads();
    int w = threadIdx.x >> 5, lane = threadIdx.x & 31;
    int l = l0 + w;
    const float* ep = g_enc_proj + (long long)(b * LL + l) * HH;
    float s = 0.0f;
#pragma unroll
    for (int it = 0; it < 8; it++) {
        int k = it * 128 + lane * 4;
        float4 e4 = *(const float4*)(ep + k);
        s += tanhf(e4.x + qs[k + 0]) * vs[k + 0];
        s += tanhf(e4.y + qs[k + 1]) * vs[k + 1];
        s += tanhf(e4.z + qs[k + 2]) * vs[k + 2];
        s += tanhf(e4.w + qs[k + 3]) * vs[k + 3];
    }
#pragma unroll
    for (int o = 16; o; o >>= 1) s += __shfl_xor_sync(0xffffffffu, s, o);
    if (!lane) g_e[b * LL + l] = s;
}

// ---------------- softmax over L per b ----------------
__global__ void softmax_kernel() {
    __shared__ float red[512];
    int b = blockIdx.x, tid = threadIdx.x;
    float v = g_e[b * LL + tid];
    red[tid] = v;
    __syncthreads();
    for (int s = 256; s; s >>= 1) {
        if (tid < s) red[tid] = fmaxf(red[tid], red[tid + s]);
        __syncthreads();
    }
    float m = red[0];
    __syncthreads();
    float e = expf(v - m);
    red[tid] = e;
    __syncthreads();
    for (int s = 256; s; s >>= 1) {
        if (tid < s) red[tid] += red[tid + s];
        __syncthreads();
    }
    g_alpha[b * LL + tid] = e / red[0];
}

// ---------------- ctx partials: sum over 64 l's ----------------
__global__ void ctxpart_kernel(const float* __restrict__ enc) {
    int s = blockIdx.x & 7;
    int hc = (blockIdx.x >> 3) & 7;
    int b = blockIdx.x >> 6;
    int h = hc * 128 + threadIdx.x;
    const float* ep = enc + (long long)(b * LL + s * 64) * HH + h;
    const float* al = g_alpha + b * LL + s * 64;
    float acc = 0.0f;
#pragma unroll 4
    for (int l = 0; l < 64; l++) acc += al[l] * ep[(long long)l * HH];
    g_ctxp[(long long)(s * BB + b) * HH + h] = acc;
}

__global__ void ctxred_kernel() {
    int b = blockIdx.x;
#pragma unroll
    for (int hi = 0; hi < 4; hi++) {
        int h = hi * 256 + threadIdx.x;
        float s = 0.0f;
#pragma unroll
        for (int p = 0; p < 8; p++) s += g_ctxp[(long long)(p * BB + b) * HH + h];
        g_ctx[b * HH + h] = s;
    }
}

// ---------------- x = concat(emb[tok], ctx) @ W_in^T + b_in ----------------
__global__ void x_kernel(const float* __restrict__ Win, const float* __restrict__ bin,
                         const float* __restrict__ emb) {
    int gw = blockIdx.x * 8 + (threadIdx.x >> 5);
    int lane = threadIdx.x & 31;
    int n = gw & (EE - 1), b = gw >> 9;
    const float* w = Win + (long long)n * (EE + HH);
    const float* er = emb + (long long)g_tok[b] * EE;
    const float* cr = g_ctx + b * HH;
    float s = 0.0f;
#pragma unroll
    for (int it = 0; it < 4; it++) {
        int k = it * 128 + lane * 4;
        float4 wv = *(const float4*)(w + k);
        float4 av = *(const float4*)(er + k);
        s += wv.x * av.x + wv.y * av.y + wv.z * av.z + wv.w * av.w;
    }
#pragma unroll
    for (int it = 0; it < 8; it++) {
        int k = it * 128 + lane * 4;
        float4 wv = *(const float4*)(w + EE + k);
        float4 av = *(const float4*)(cr + k);
        s += wv.x * av.x + wv.y * av.y + wv.z * av.z + wv.w * av.w;
    }
#pragma unroll
    for (int o = 16; o; o >>= 1) s += __shfl_xor_sync(0xffffffffu, s, o);
    if (!lane) g_x[b * EE + n] = s + bin[n];
}

// ---------------- LSTM elementwise cell update ----------------
__global__ void lstm_elt(int layer) {
    int id = blockIdx.x * blockDim.x + threadIdx.x;   // 32768
    int b = id >> 10, hh = id & 1023;
    const float* p0 = g_gp0 + b * G4H;
    const float* p1 = g_gp1 + b * G4H;
    float gi = p0[hh] + p1[hh];
    float gf = p0[1024 + hh] + p1[1024 + hh];
    float gg = p0[2048 + hh] + p1[2048 + hh];
    float go = p0[3072 + hh] + p1[3072 + hh];
    float* c = g_c + layer * BB * HH;
    float* h = g_h + layer * BB * HH;
    float cn = acc_sig(gf) * c[b * HH + hh] + acc_sig(gi) * tanhf(gg);
    c[b * HH + hh] = cn;
    h[b * HH + hh] = acc_sig(go) * tanhf(cn);
}

// ---------------- argmax over V ----------------
__global__ void argmax_kernel(float* __restrict__ out, int t) {
    __shared__ float sv[256];
    __shared__ int si[256];
    int b = blockIdx.x, tid = threadIdx.x;
    const float* p = out + (long long)b * TT * VV + (long long)t * VV;
    float best = -3.4e38f;
    int bi = 0;
    for (int v = tid; v < VV; v += 256) {
        float x = p[v];
        if (x > best) { best = x; bi = v; }
    }
    sv[tid] = best; si[tid] = bi;
    __syncthreads();
    for (int s = 128; s; s >>= 1) {
        if (tid < s) {
            if (sv[tid + s] > sv[tid] || (sv[tid + s] == sv[tid] && si[tid + s] < si[tid])) {
                sv[tid] = sv[tid + s]; si[tid] = si[tid + s];
            }
        }
        __syncthreads();
    }
    if (!tid) {
        g_tok[b] = si[0];
        out[(long long)BB * TT * VV + b * TT + t] = (float)si[0];
    }
}

// ---------------- launch ----------------
extern "C" void kernel_launch(void* const* d_in, const int* in_sizes, int n_in,
                              void* d_out, int out_size) {
    const float* enc_output = (const float*)d_in[0];
    const int*   trg        = (const int*)d_in[1];     // int32! (JAX x64 disabled)
    const float* emb        = (const float*)d_in[2];
    const float* W_att_enc  = (const float*)d_in[3];
    const float* b_att_enc  = (const float*)d_in[4];
    const float* W_att_dec  = (const float*)d_in[5];
    const float* b_att_dec  = (const float*)d_in[6];
    const float* v_att      = (const float*)d_in[7];
    const float* W_in       = (const float*)d_in[8];
    const float* b_in       = (const float*)d_in[9];
    const float* W_ih0      = (const float*)d_in[10];
    const float* W_hh0      = (const float*)d_in[11];
    const float* b_ih0      = (const float*)d_in[12];
    const float* b_hh0      = (const float*)d_in[13];
    const float* W_ih1      = (const float*)d_in[14];
    const float* W_hh1      = (const float*)d_in[15];
    const float* b_ih1      = (const float*)d_in[16];
    const float* b_hh1      = (const float*)d_in[17];
    const float* W_fc       = (const float*)d_in[18];
    const float* b_fc       = (const float*)d_in[19];
    float* out = (float*)d_out;

    init_kernel<<<(BB * VV + 255) / 256, 256>>>(trg, out);

    // enc_proj = enc_output @ W_att_enc^T + b_att_enc   [B*L, H]
    gemm_m32<<<dim3(HH / 64, (BB * LL) / 32), 128>>>(
        W_att_enc, 0, enc_output, b_att_enc, 1, nullptr, HH, HH, (long long)HH);

    for (int t = 1; t < TT; t++) {
        q_kernel<<<(BB * HH / 8), 256>>>(W_att_dec, b_att_dec);
        energy_kernel<<<BB * (LL / 8), 256>>>(v_att);
        softmax_kernel<<<BB, 512>>>();
        ctxpart_kernel<<<BB * 8 * 8, 128>>>(enc_output);
        ctxred_kernel<<<BB, 256>>>();
        x_kernel<<<(BB * EE / 8), 256>>>(W_in, b_in, emb);

        gemm_m32<<<G4H / 64, 128>>>(W_ih0, 1, nullptr, b_ih0, 2, nullptr, G4H, EE, (long long)G4H);
        gemm_m32<<<G4H / 64, 128>>>(W_hh0, 2, nullptr, b_hh0, 3, nullptr, G4H, HH, (long long)G4H);
        lstm_elt<<<BB * HH / 256, 256>>>(0);

        gemm_m32<<<G4H / 64, 128>>>(W_ih1, 2, nullptr, b_ih1, 2, nullptr, G4H, HH, (long long)G4H);
        gemm_m32<<<G4H / 64, 128>>>(W_hh1, 3, nullptr, b_hh1, 3, nullptr, G4H, HH, (long long)G4H);
        lstm_elt<<<BB * HH / 256, 256>>>(1);

        gemm_m32<<<VV / 64, 128>>>(W_fc, 3, nullptr, b_fc, 0, out + (long long)t * VV,
                                   VV, HH, (long long)TT * VV);
        argmax_kernel<<<BB, 256>>>(out, t);
    }
}

// round 3
// speedup vs baseline: 1.7676x; 1.7676x over previous
#include <cuda_runtime.h>
#include <cuda_bf16.h>
#include <stdint.h>

#define BB 32
#define LL 512
#define EE 512
#define HH 1024
#define VV 32000
#define TT 64
#define G4H 4096

// ---------------- scratch (device globals; no allocation allowed) ----------------
__device__ float g_enc_proj[BB * LL * HH];   // 67 MB
__device__ float g_h[2 * BB * HH];
__device__ float g_c[2 * BB * HH];
__device__ float g_q[BB * HH];
__device__ float g_e[BB * LL];
__device__ float g_alpha[BB * LL];
__device__ float g_ctxp[8 * BB * HH];
__device__ float g_ctx[BB * HH];
__device__ float g_x[BB * EE];
__device__ float g_gp0[BB * G4H];
__device__ float g_gp1[BB * G4H];
__device__ int   g_tok[BB];

// bf16 hi/lo split weights
__device__ __nv_bfloat16 g_wenc_hi[HH * HH],  g_wenc_lo[HH * HH];
__device__ __nv_bfloat16 g_wih0_hi[G4H * EE], g_wih0_lo[G4H * EE];
__device__ __nv_bfloat16 g_whh0_hi[G4H * HH], g_whh0_lo[G4H * HH];
__device__ __nv_bfloat16 g_wih1_hi[G4H * HH], g_wih1_lo[G4H * HH];
__device__ __nv_bfloat16 g_whh1_hi[G4H * HH], g_whh1_lo[G4H * HH];
__device__ __nv_bfloat16 g_wfc_hi[(long long)VV * HH], g_wfc_lo[(long long)VV * HH];

__device__ __forceinline__ float acc_sig(float x) {
    return 1.0f / (1.0f + expf(-x));
}

// ---------------- init ----------------
__global__ void init_kernel(const int* __restrict__ trg, float* __restrict__ out) {
    int gid = blockIdx.x * blockDim.x + threadIdx.x;
    if (gid < BB * VV) {
        int b = gid / VV, v = gid - b * VV;
        out[(long long)b * TT * VV + v] = 0.0f;
    }
    if (gid < 2 * BB * HH) { g_h[gid] = 0.0f; g_c[gid] = 0.0f; }
    if (gid < BB) {
        g_tok[gid] = trg[gid * TT];                            // trg[:,0] (int32)
        out[(long long)BB * TT * VV + gid * TT] = 1.0f;        // _pred[:,0] = sos
    }
}

// ---------------- weight split fp32 -> bf16 hi + bf16 lo ----------------
__global__ void split_w_kernel(const float* __restrict__ src,
                               __nv_bfloat16* __restrict__ hi,
                               __nv_bfloat16* __restrict__ lo, int n4) {
    int i = blockIdx.x * 256 + threadIdx.x;
    if (i >= n4) return;
    long long idx = (long long)i * 4;
    float4 v = *(const float4*)(src + idx);
    float f[4] = {v.x, v.y, v.z, v.w};
    __nv_bfloat16 h[4]; __nv_bfloat16 l[4];
#pragma unroll
    for (int j = 0; j < 4; j++) {
        h[j] = __float2bfloat16(f[j]);
        l[j] = __float2bfloat16(f[j] - __bfloat162float(h[j]));
    }
    __nv_bfloat162 hp0; hp0.x = h[0]; hp0.y = h[1];
    __nv_bfloat162 hp1; hp1.x = h[2]; hp1.y = h[3];
    __nv_bfloat162 lp0; lp0.x = l[0]; lp0.y = l[1];
    __nv_bfloat162 lp1; lp1.x = l[2]; lp1.y = l[3];
    *(uint32_t*)(hi + idx)     = *(uint32_t*)&hp0;
    *(uint32_t*)(hi + idx + 2) = *(uint32_t*)&hp1;
    *(uint32_t*)(lo + idx)     = *(uint32_t*)&lp0;
    *(uint32_t*)(lo + idx + 2) = *(uint32_t*)&lp1;
}

// ---------------- bf16-split MMA GEMM core: out[m(32), n] = bias[n] + act @ W^T ----------
__device__ __forceinline__ void mma_bf16(float* d, uint32_t a0, uint32_t a1, uint32_t a2,
                                         uint32_t a3, uint32_t b0, uint32_t b1) {
    asm volatile(
        "mma.sync.aligned.m16n8k16.row.col.f32.bf16.bf16.f32 "
        "{%0,%1,%2,%3}, {%4,%5,%6,%7}, {%8,%9}, {%0,%1,%2,%3};"
        : "+f"(d[0]), "+f"(d[1]), "+f"(d[2]), "+f"(d[3])
        : "r"(a0), "r"(a1), "r"(a2), "r"(a3), "r"(b0), "r"(b1));
}

struct SmemA {
    uint32_t hi[2][32][36];   // packed bf16 pairs, stride 36 => conflict-free frag loads
    uint32_t lo[2][32][36];
};

__device__ __forceinline__ void gemm_core(
    SmemA* sm,
    const __nv_bfloat16* __restrict__ Whi, const __nv_bfloat16* __restrict__ Wlo,
    const float* __restrict__ act, int actStride,
    const float* __restrict__ bias,
    float* __restrict__ out, long long outStride,
    int K, int n0)
{
    const int tid = threadIdx.x;
    const int wid = tid >> 5, lane = tid & 31;
    const int g = lane >> 2, tq = lane & 3;

    const int nB = n0 + wid * 8 + g;                 // B-frag n row
    const __nv_bfloat16* wh = Whi + (long long)nB * K;
    const __nv_bfloat16* wl = Wlo + (long long)nB * K;

    float d0[4] = {0.f, 0.f, 0.f, 0.f};
    float d1[4] = {0.f, 0.f, 0.f, 0.f};

    const int srow = tid >> 3;           // 0..31
    const int scol = (tid & 7) * 8;      // 0..56
    const int nch = K >> 6;

    // stage chunk 0
    {
        const float* ap = act + srow * actStride + scol;
        float4 v0 = *(const float4*)ap;
        float4 v1 = *(const float4*)(ap + 4);
        float f[8] = {v0.x, v0.y, v0.z, v0.w, v1.x, v1.y, v1.z, v1.w};
#pragma unroll
        for (int j = 0; j < 4; j++) {
            __nv_bfloat16 h0 = __float2bfloat16(f[2 * j]);
            __nv_bfloat16 h1 = __float2bfloat16(f[2 * j + 1]);
            __nv_bfloat162 hp; hp.x = h0; hp.y = h1;
            __nv_bfloat162 lp;
            lp.x = __float2bfloat16(f[2 * j] - __bfloat162float(h0));
            lp.y = __float2bfloat16(f[2 * j + 1] - __bfloat162float(h1));
            sm->hi[0][srow][scol / 2 + j] = *(uint32_t*)&hp;
            sm->lo[0][srow][scol / 2 + j] = *(uint32_t*)&lp;
        }
    }
    __syncthreads();

    for (int c = 0; c < nch; c++) {
        const int buf = c & 1;
        // preload all B fragments for the 4 k16-steps of this 64-chunk
        uint32_t bh[4][2], bl[4][2];
        const __nv_bfloat16* whc = wh + c * 64;
        const __nv_bfloat16* wlc = wl + c * 64;
#pragma unroll
        for (int ks = 0; ks < 4; ks++) {
            bh[ks][0] = *(const uint32_t*)(whc + ks * 16 + 2 * tq);
            bh[ks][1] = *(const uint32_t*)(whc + ks * 16 + 2 * tq + 8);
            bl[ks][0] = *(const uint32_t*)(wlc + ks * 16 + 2 * tq);
            bl[ks][1] = *(const uint32_t*)(wlc + ks * 16 + 2 * tq + 8);
        }
#pragma unroll
        for (int ks = 0; ks < 4; ks++) {
            const int p0 = ks * 8 + tq, p1 = p0 + 4;
            // m-tile 0 (rows 0-15)
            {
                uint32_t ah0 = sm->hi[buf][g][p0],      ah1 = sm->hi[buf][g + 8][p0];
                uint32_t ah2 = sm->hi[buf][g][p1],      ah3 = sm->hi[buf][g + 8][p1];
                uint32_t al0 = sm->lo[buf][g][p0],      al1 = sm->lo[buf][g + 8][p0];
                uint32_t al2 = sm->lo[buf][g][p1],      al3 = sm->lo[buf][g + 8][p1];
                mma_bf16(d0, ah0, ah1, ah2, ah3, bh[ks][0], bh[ks][1]);
                mma_bf16(d0, ah0, ah1, ah2, ah3, bl[ks][0], bl[ks][1]);
                mma_bf16(d0, al0, al1, al2, al3, bh[ks][0], bh[ks][1]);
            }
            // m-tile 1 (rows 16-31)
            {
                uint32_t ah0 = sm->hi[buf][16 + g][p0], ah1 = sm->hi[buf][24 + g][p0];
                uint32_t ah2 = sm->hi[buf][16 + g][p1], ah3 = sm->hi[buf][24 + g][p1];
                uint32_t al0 = sm->lo[buf][16 + g][p0], al1 = sm->lo[buf][24 + g][p0];
                uint32_t al2 = sm->lo[buf][16 + g][p1], al3 = sm->lo[buf][24 + g][p1];
                mma_bf16(d1, ah0, ah1, ah2, ah3, bh[ks][0], bh[ks][1]);
                mma_bf16(d1, ah0, ah1, ah2, ah3, bl[ks][0], bl[ks][1]);
                mma_bf16(d1, al0, al1, al2, al3, bh[ks][0], bh[ks][1]);
            }
        }
        if (c + 1 < nch) {
            const float* ap = act + srow * actStride + (c + 1) * 64 + scol;
            float4 v0 = *(const float4*)ap;
            float4 v1 = *(const float4*)(ap + 4);
            float f[8] = {v0.x, v0.y, v0.z, v0.w, v1.x, v1.y, v1.z, v1.w};
            __syncthreads();   // all warps done reading buf^1 (chunk c-1)
            const int nb = buf ^ 1;
#pragma unroll
            for (int j = 0; j < 4; j++) {
                __nv_bfloat16 h0 = __float2bfloat16(f[2 * j]);
                __nv_bfloat16 h1 = __float2bfloat16(f[2 * j + 1]);
                __nv_bfloat162 hp; hp.x = h0; hp.y = h1;
                __nv_bfloat162 lp;
                lp.x = __float2bfloat16(f[2 * j] - __bfloat162float(h0));
                lp.y = __float2bfloat16(f[2 * j + 1] - __bfloat162float(h1));
                sm->hi[nb][srow][scol / 2 + j] = *(uint32_t*)&hp;
                sm->lo[nb][srow][scol / 2 + j] = *(uint32_t*)&lp;
            }
            __syncthreads();
        }
    }

    // epilogue: D frags -> out (+bias)
    const int nc = n0 + wid * 8 + 2 * tq;
    float2 bv = *(const float2*)(bias + nc);
    float2 r;
    r.x = d0[0] + bv.x; r.y = d0[1] + bv.y;
    *(float2*)(out + (long long)g * outStride + nc) = r;
    r.x = d0[2] + bv.x; r.y = d0[3] + bv.y;
    *(float2*)(out + (long long)(g + 8) * outStride + nc) = r;
    r.x = d1[0] + bv.x; r.y = d1[1] + bv.y;
    *(float2*)(out + (long long)(16 + g) * outStride + nc) = r;
    r.x = d1[2] + bv.x; r.y = d1[3] + bv.y;
    *(float2*)(out + (long long)(24 + g) * outStride + nc) = r;
}

// ---------------- GEMM wrappers ----------------
__global__ __launch_bounds__(256) void gemm_encproj_mma(const float* __restrict__ enc,
                                                        const float* __restrict__ bias) {
    __shared__ SmemA sm;
    gemm_core(&sm, g_wenc_hi, g_wenc_lo,
              enc + (long long)blockIdx.y * 32 * HH, HH, bias,
              g_enc_proj + (long long)blockIdx.y * 32 * HH, HH, HH, blockIdx.x * 64);
}

__global__ __launch_bounds__(256) void gemm_fc_mma(const float* __restrict__ bias,
                                                   float* __restrict__ outp) {
    __shared__ SmemA sm;
    gemm_core(&sm, g_wfc_hi, g_wfc_lo, g_h + BB * HH, HH, bias,
              outp, (long long)TT * VV, HH, blockIdx.x * 64);
}

__global__ __launch_bounds__(256) void gemm_gates_mma(int layer,
                                                      const float* __restrict__ b_ih,
                                                      const float* __restrict__ b_hh) {
    __shared__ SmemA sm;
    const int src = blockIdx.x >> 6;
    const int n0 = (blockIdx.x & 63) * 64;
    const __nv_bfloat16 *Whi, *Wlo;
    const float* act; const float* bias;
    float* out; int K, as_;
    if (layer == 0) {
        if (src == 0) { Whi = g_wih0_hi; Wlo = g_wih0_lo; act = g_x;          K = EE; as_ = EE; out = g_gp0; bias = b_ih; }
        else          { Whi = g_whh0_hi; Wlo = g_whh0_lo; act = g_h;          K = HH; as_ = HH; out = g_gp1; bias = b_hh; }
    } else {
        if (src == 0) { Whi = g_wih1_hi; Wlo = g_wih1_lo; act = g_h;          K = HH; as_ = HH; out = g_gp0; bias = b_ih; }
        else          { Whi = g_whh1_hi; Wlo = g_whh1_lo; act = g_h + BB*HH;  K = HH; as_ = HH; out = g_gp1; bias = b_hh; }
    }
    gemm_core(&sm, Whi, Wlo, act, as_, bias, out, G4H, K, n0);
}

// ---------------- q = h1 @ W_att_dec^T + b  (warp per (b,n)) ----------------
__global__ void q_kernel(const float* __restrict__ Wd, const float* __restrict__ bd) {
    int gw = blockIdx.x * 8 + (threadIdx.x >> 5);
    int lane = threadIdx.x & 31;
    int n = gw & (HH - 1), b = gw >> 10;
    const float* w = Wd + (long long)n * HH;
    const float* a = g_h + BB * HH + b * HH;   // h1
    float s = 0.0f;
#pragma unroll
    for (int it = 0; it < 8; it++) {
        int k = it * 128 + lane * 4;
        float4 wv = *(const float4*)(w + k);
        float4 av = *(const float4*)(a + k);
        s += wv.x * av.x + wv.y * av.y + wv.z * av.z + wv.w * av.w;
    }
#pragma unroll
    for (int o = 16; o; o >>= 1) s += __shfl_xor_sync(0xffffffffu, s, o);
    if (!lane) g_q[b * HH + n] = s + bd[n];
}

// ---------------- energy: e[b,l] = sum_h tanh(enc_proj + q) * v_att ----------------
__global__ void energy_kernel(const float* __restrict__ v_att) {
    __shared__ float qs[HH];
    __shared__ float vs[HH];
    int b = blockIdx.x >> 6;
    int l0 = (blockIdx.x & 63) << 3;
    {
        int i = threadIdx.x * 4;
        *(float4*)&qs[i] = *(const float4*)&g_q[b * HH + i];
        *(float4*)&vs[i] = *(const float4*)&v_att[i];
    }
    __syncthreads();
    int w = threadIdx.x >> 5, lane = threadIdx.x & 31;
    int l = l0 + w;
    const float* ep = g_enc_proj + (long long)(b * LL + l) * HH;
    float s = 0.0f;
#pragma unroll
    for (int it = 0; it < 8; it++) {
        int k = it * 128 + lane * 4;
        float4 e4 = *(const float4*)(ep + k);
        s += tanhf(e4.x + qs[k + 0]) * vs[k + 0];
        s += tanhf(e4.y + qs[k + 1]) * vs[k + 1];
        s += tanhf(e4.z + qs[k + 2]) * vs[k + 2];
        s += tanhf(e4.w + qs[k + 3]) * vs[k + 3];
    }
#pragma unroll
    for (int o = 16; o; o >>= 1) s += __shfl_xor_sync(0xffffffffu, s, o);
    if (!lane) g_e[b * LL + l] = s;
}

// ---------------- softmax over L per b ----------------
__global__ void softmax_kernel() {
    __shared__ float red[512];
    int b = blockIdx.x, tid = threadIdx.x;
    float v = g_e[b * LL + tid];
    red[tid] = v;
    __syncthreads();
    for (int s = 256; s; s >>= 1) {
        if (tid < s) red[tid] = fmaxf(red[tid], red[tid + s]);
        __syncthreads();
    }
    float m = red[0];
    __syncthreads();
    float e = expf(v - m);
    red[tid] = e;
    __syncthreads();
    for (int s = 256; s; s >>= 1) {
        if (tid < s) red[tid] += red[tid + s];
        __syncthreads();
    }
    g_alpha[b * LL + tid] = e / red[0];
}

// ---------------- ctx partials ----------------
__global__ void ctxpart_kernel(const float* __restrict__ enc) {
    int s = blockIdx.x & 7;
    int hc = (blockIdx.x >> 3) & 7;
    int b = blockIdx.x >> 6;
    int h = hc * 128 + threadIdx.x;
    const float* ep = enc + (long long)(b * LL + s * 64) * HH + h;
    const float* al = g_alpha + b * LL + s * 64;
    float acc = 0.0f;
#pragma unroll 4
    for (int l = 0; l < 64; l++) acc += al[l] * ep[(long long)l * HH];
    g_ctxp[(long long)(s * BB + b) * HH + h] = acc;
}

__global__ void ctxred_kernel() {
    int b = blockIdx.x;
#pragma unroll
    for (int hi = 0; hi < 4; hi++) {
        int h = hi * 256 + threadIdx.x;
        float s = 0.0f;
#pragma unroll
        for (int p = 0; p < 8; p++) s += g_ctxp[(long long)(p * BB + b) * HH + h];
        g_ctx[b * HH + h] = s;
    }
}

// ---------------- x = concat(emb[tok], ctx) @ W_in^T + b_in ----------------
__global__ void x_kernel(const float* __restrict__ Win, const float* __restrict__ bin,
                         const float* __restrict__ emb) {
    int gw = blockIdx.x * 8 + (threadIdx.x >> 5);
    int lane = threadIdx.x & 31;
    int n = gw & (EE - 1), b = gw >> 9;
    const float* w = Win + (long long)n * (EE + HH);
    const float* er = emb + (long long)g_tok[b] * EE;
    const float* cr = g_ctx + b * HH;
    float s = 0.0f;
#pragma unroll
    for (int it = 0; it < 4; it++) {
        int k = it * 128 + lane * 4;
        float4 wv = *(const float4*)(w + k);
        float4 av = *(const float4*)(er + k);
        s += wv.x * av.x + wv.y * av.y + wv.z * av.z + wv.w * av.w;
    }
#pragma unroll
    for (int it = 0; it < 8; it++) {
        int k = it * 128 + lane * 4;
        float4 wv = *(const float4*)(w + EE + k);
        float4 av = *(const float4*)(cr + k);
        s += wv.x * av.x + wv.y * av.y + wv.z * av.z + wv.w * av.w;
    }
#pragma unroll
    for (int o = 16; o; o >>= 1) s += __shfl_xor_sync(0xffffffffu, s, o);
    if (!lane) g_x[b * EE + n] = s + bin[n];
}

// ---------------- LSTM elementwise cell update ----------------
__global__ void lstm_elt(int layer) {
    int id = blockIdx.x * blockDim.x + threadIdx.x;   // 32768
    int b = id >> 10, hh = id & 1023;
    const float* p0 = g_gp0 + b * G4H;
    const float* p1 = g_gp1 + b * G4H;
    float gi = p0[hh] + p1[hh];
    float gf = p0[1024 + hh] + p1[1024 + hh];
    float gg = p0[2048 + hh] + p1[2048 + hh];
    float go = p0[3072 + hh] + p1[3072 + hh];
    float* c = g_c + layer * BB * HH;
    float* h = g_h + layer * BB * HH;
    float cn = acc_sig(gf) * c[b * HH + hh] + acc_sig(gi) * tanhf(gg);
    c[b * HH + hh] = cn;
    h[b * HH + hh] = acc_sig(go) * tanhf(cn);
}

// ---------------- argmax over V ----------------
__global__ void argmax_kernel(float* __restrict__ out, int t) {
    __shared__ float sv[256];
    __shared__ int si[256];
    int b = blockIdx.x, tid = threadIdx.x;
    const float* p = out + (long long)b * TT * VV + (long long)t * VV;
    float best = -3.4e38f;
    int bi = 0;
    for (int v = tid; v < VV; v += 256) {
        float x = p[v];
        if (x > best) { best = x; bi = v; }
    }
    sv[tid] = best; si[tid] = bi;
    __syncthreads();
    for (int s = 128; s; s >>= 1) {
        if (tid < s) {
            if (sv[tid + s] > sv[tid] || (sv[tid + s] == sv[tid] && si[tid + s] < si[tid])) {
                sv[tid] = sv[tid + s]; si[tid] = si[tid + s];
            }
        }
        __syncthreads();
    }
    if (!tid) {
        g_tok[b] = si[0];
        out[(long long)BB * TT * VV + b * TT + t] = (float)si[0];
    }
}

// ---------------- launch ----------------
static void split_one(const void* symbol, const float* src, long long n) {
    void* p_hi = nullptr;
    cudaGetSymbolAddress(&p_hi, symbol);
    // lo array immediately follows? No — separate symbols handled by caller.
    (void)p_hi; (void)src; (void)n;
}

extern "C" void kernel_launch(void* const* d_in, const int* in_sizes, int n_in,
                              void* d_out, int out_size) {
    const float* enc_output = (const float*)d_in[0];
    const int*   trg        = (const int*)d_in[1];     // int32 (JAX x64 disabled)
    const float* emb        = (const float*)d_in[2];
    const float* W_att_enc  = (const float*)d_in[3];
    const float* b_att_enc  = (const float*)d_in[4];
    const float* W_att_dec  = (const float*)d_in[5];
    const float* b_att_dec  = (const float*)d_in[6];
    const float* v_att      = (const float*)d_in[7];
    const float* W_in       = (const float*)d_in[8];
    const float* b_in       = (const float*)d_in[9];
    const float* W_ih0      = (const float*)d_in[10];
    const float* W_hh0      = (const float*)d_in[11];
    const float* b_ih0      = (const float*)d_in[12];
    const float* b_hh0      = (const float*)d_in[13];
    const float* W_ih1      = (const float*)d_in[14];
    const float* W_hh1      = (const float*)d_in[15];
    const float* b_ih1      = (const float*)d_in[16];
    const float* b_hh1      = (const float*)d_in[17];
    const float* W_fc       = (const float*)d_in[18];
    const float* b_fc       = (const float*)d_in[19];
    float* out = (float*)d_out;

    init_kernel<<<(BB * VV + 255) / 256, 256>>>(trg, out);

    // split weights into bf16 hi/lo
    void *enc_hi, *enc_lo, *ih0_hi, *ih0_lo, *hh0_hi, *hh0_lo;
    void *ih1_hi, *ih1_lo, *hh1_hi, *hh1_lo, *fc_hi, *fc_lo;
    cudaGetSymbolAddress(&enc_hi, g_wenc_hi); cudaGetSymbolAddress(&enc_lo, g_wenc_lo);
    cudaGetSymbolAddress(&ih0_hi, g_wih0_hi); cudaGetSymbolAddress(&ih0_lo, g_wih0_lo);
    cudaGetSymbolAddress(&hh0_hi, g_whh0_hi); cudaGetSymbolAddress(&hh0_lo, g_whh0_lo);
    cudaGetSymbolAddress(&ih1_hi, g_wih1_hi); cudaGetSymbolAddress(&ih1_lo, g_wih1_lo);
    cudaGetSymbolAddress(&hh1_hi, g_whh1_hi); cudaGetSymbolAddress(&hh1_lo, g_whh1_lo);
    cudaGetSymbolAddress(&fc_hi,  g_wfc_hi);  cudaGetSymbolAddress(&fc_lo,  g_wfc_lo);

    {
        long long n;
        n = (long long)HH * HH / 4;
        split_w_kernel<<<(int)((n + 255) / 256), 256>>>(W_att_enc, (__nv_bfloat16*)enc_hi, (__nv_bfloat16*)enc_lo, (int)n);
        n = (long long)G4H * EE / 4;
        split_w_kernel<<<(int)((n + 255) / 256), 256>>>(W_ih0, (__nv_bfloat16*)ih0_hi, (__nv_bfloat16*)ih0_lo, (int)n);
        n = (long long)G4H * HH / 4;
        split_w_kernel<<<(int)((n + 255) / 256), 256>>>(W_hh0, (__nv_bfloat16*)hh0_hi, (__nv_bfloat16*)hh0_lo, (int)n);
        split_w_kernel<<<(int)((n + 255) / 256), 256>>>(W_ih1, (__nv_bfloat16*)ih1_hi, (__nv_bfloat16*)ih1_lo, (int)n);
        split_w_kernel<<<(int)((n + 255) / 256), 256>>>(W_hh1, (__nv_bfloat16*)hh1_hi, (__nv_bfloat16*)hh1_lo, (int)n);
        n = (long long)VV * HH / 4;
        split_w_kernel<<<(int)((n + 255) / 256), 256>>>(W_fc, (__nv_bfloat16*)fc_hi, (__nv_bfloat16*)fc_lo, (int)n);
    }

    // enc_proj = enc_output @ W_att_enc^T + b_att_enc   [B*L, H]
    gemm_encproj_mma<<<dim3(HH / 64, (BB * LL) / 32), 256>>>(enc_output, b_att_enc);

    for (int t = 1; t < TT; t++) {
        q_kernel<<<(BB * HH / 8), 256>>>(W_att_dec, b_att_dec);
        energy_kernel<<<BB * (LL / 8), 256>>>(v_att);
        softmax_kernel<<<BB, 512>>>();
        ctxpart_kernel<<<BB * 8 * 8, 128>>>(enc_output);
        ctxred_kernel<<<BB, 256>>>();
        x_kernel<<<(BB * EE / 8), 256>>>(W_in, b_in, emb);

        gemm_gates_mma<<<128, 256>>>(0, b_ih0, b_hh0);
        lstm_elt<<<BB * HH / 256, 256>>>(0);

        gemm_gates_mma<<<128, 256>>>(1, b_ih1, b_hh1);
        lstm_elt<<<BB * HH / 256, 256>>>(1);

        gemm_fc_mma<<<VV / 64, 256>>>(b_fc, out + (long long)t * VV);
        argmax_kernel<<<BB, 256>>>(out, t);
    }
}

// round 5
// speedup vs baseline: 1.9887x; 1.1251x over previous
#include <cuda_runtime.h>
#include <cuda_bf16.h>
#include <stdint.h>

#define BB 32
#define LL 512
#define EE 512
#define HH 1024
#define VV 32000
#define TT 64
#define G4H 4096

// ---------------- scratch (device globals; no allocation allowed) ----------------
__device__ float g_enc_proj[BB * LL * HH];   // 67 MB
__device__ float g_h[2 * BB * HH];
__device__ float g_c[2 * BB * HH];
__device__ float g_q[BB * HH];
__device__ float g_e[BB * LL];
__device__ float g_ctx[BB * HH];
__device__ float g_gp0[BB * G4H];
__device__ float g_gp1[BB * G4H];
__device__ float g_gp2[BB * G4H];
__device__ float g_gp3[BB * G4H];
__device__ int   g_tok[BB];
__device__ unsigned long long g_amax[BB];

// bf16 hi/lo split weights
__device__ __nv_bfloat16 g_wenc_hi[HH * HH],  g_wenc_lo[HH * HH];
__device__ __nv_bfloat16 g_wih0_hi[G4H * EE], g_wih0_lo[G4H * EE];
__device__ __nv_bfloat16 g_whh0_hi[G4H * HH], g_whh0_lo[G4H * HH];
__device__ __nv_bfloat16 g_wih1_hi[G4H * HH], g_wih1_lo[G4H * HH];
__device__ __nv_bfloat16 g_whh1_hi[G4H * HH], g_whh1_lo[G4H * HH];
__device__ __nv_bfloat16 g_wfc_hi[(long long)VV * HH], g_wfc_lo[(long long)VV * HH];
// bf16 hi/lo split activations
__device__ __nv_bfloat16 g_ehi[BB * LL * HH], g_elo[BB * LL * HH];   // enc_output split
__device__ __nv_bfloat16 g_xhi[BB * EE], g_xlo[BB * EE];
__device__ __nv_bfloat16 g_hhi[2 * BB * HH], g_hlo[2 * BB * HH];

__device__ __forceinline__ float acc_sig(float x) {
    return 1.0f / (1.0f + expf(-x));
}
// exp-based tanh: abs err ~1e-7 (safe for the recurrent/argmax chain)
__device__ __forceinline__ float fast_tanh(float x) {
    float xc = fminf(fmaxf(x, -15.0f), 15.0f);
    float t = __expf(2.0f * xc);
    return __fdividef(t - 1.0f, t + 1.0f);
}

__device__ __forceinline__ unsigned long long pack_key(float f, int idx) {
    unsigned int b = __float_as_uint(f);
    b = (b & 0x80000000u) ? ~b : (b | 0x80000000u);   // monotonic float key
    return ((unsigned long long)b << 32) | (unsigned int)(VV - idx); // ties -> smaller idx wins
}
__device__ __forceinline__ unsigned long long umax64(unsigned long long a, unsigned long long b) {
    return a > b ? a : b;
}

// ---------------- init ----------------
__global__ void init_kernel(const int* __restrict__ trg, float* __restrict__ out) {
    int gid = blockIdx.x * blockDim.x + threadIdx.x;
    if (gid < BB * VV) {
        int b = gid / VV, v = gid - b * VV;
        out[(long long)b * TT * VV + v] = 0.0f;        // outputs[:,0,:] = 0
    }
    if (gid < 2 * BB * HH) {
        g_h[gid] = 0.0f; g_c[gid] = 0.0f;
        g_hhi[gid] = __float2bfloat16(0.0f);
        g_hlo[gid] = __float2bfloat16(0.0f);
    }
    if (gid < BB) {
        g_tok[gid] = trg[gid * TT];                    // trg[:,0] (int32)
        out[(long long)BB * TT * VV + gid * TT] = 1.0f; // _pred[:,0] = sos
    }
}

// ---------------- fp32 -> bf16 hi + lo split (weights and enc_output) ----------------
__global__ void split_w_kernel(const float* __restrict__ src,
                               __nv_bfloat16* __restrict__ hi,
                               __nv_bfloat16* __restrict__ lo, int n4) {
    int i = blockIdx.x * 256 + threadIdx.x;
    if (i >= n4) return;
    long long idx = (long long)i * 4;
    float4 v = *(const float4*)(src + idx);
    float f[4] = {v.x, v.y, v.z, v.w};
    __nv_bfloat16 h[4], l[4];
#pragma unroll
    for (int j = 0; j < 4; j++) {
        h[j] = __float2bfloat16(f[j]);
        l[j] = __float2bfloat16(f[j] - __bfloat162float(h[j]));
    }
    __nv_bfloat162 hp0; hp0.x = h[0]; hp0.y = h[1];
    __nv_bfloat162 hp1; hp1.x = h[2]; hp1.y = h[3];
    __nv_bfloat162 lp0; lp0.x = l[0]; lp0.y = l[1];
    __nv_bfloat162 lp1; lp1.x = l[2]; lp1.y = l[3];
    *(uint32_t*)(hi + idx)     = *(uint32_t*)&hp0;
    *(uint32_t*)(hi + idx + 2) = *(uint32_t*)&hp1;
    *(uint32_t*)(lo + idx)     = *(uint32_t*)&lp0;
    *(uint32_t*)(lo + idx + 2) = *(uint32_t*)&lp1;
}

// ---------------- bf16-split MMA GEMM core (act preconverted to bf16 hi/lo) ----------
__device__ __forceinline__ void mma_bf16(float* d, uint32_t a0, uint32_t a1, uint32_t a2,
                                         uint32_t a3, uint32_t b0, uint32_t b1) {
    asm volatile(
        "mma.sync.aligned.m16n8k16.row.col.f32.bf16.bf16.f32 "
        "{%0,%1,%2,%3}, {%4,%5,%6,%7}, {%8,%9}, {%0,%1,%2,%3};"
        : "+f"(d[0]), "+f"(d[1]), "+f"(d[2]), "+f"(d[3])
        : "r"(a0), "r"(a1), "r"(a2), "r"(a3), "r"(b0), "r"(b1));
}

struct SmemA {
    uint32_t hi[2][32][36];   // stride 36 => conflict-free frag loads
    uint32_t lo[2][32][36];
};

__device__ __forceinline__ void gemm_core(
    SmemA* sm,
    const __nv_bfloat16* __restrict__ Whi, const __nv_bfloat16* __restrict__ Wlo,
    long long wStride,
    const uint32_t* __restrict__ Ahi, const uint32_t* __restrict__ Alo, int aStrideW,
    const float* __restrict__ bias,
    float* __restrict__ out, long long outStride,
    int K, int n0,
    unsigned long long* amax)
{
    const int tid = threadIdx.x;
    const int wid = tid >> 5, lane = tid & 31;
    const int g = lane >> 2, tq = lane & 3;

    const int nB = n0 + wid * 8 + g;
    const __nv_bfloat16* wh = Whi + (long long)nB * wStride;
    const __nv_bfloat16* wl = Wlo + (long long)nB * wStride;

    float d0[4] = {0.f, 0.f, 0.f, 0.f};
    float d1[4] = {0.f, 0.f, 0.f, 0.f};

    const int srow = tid >> 3;
    const int scolg = tid & 7;
    const int nch = K >> 6;
    const uint32_t* arow_h = Ahi + (long long)srow * aStrideW + scolg * 4;
    const uint32_t* arow_l = Alo + (long long)srow * aStrideW + scolg * 4;

    {   // stage chunk 0
        uint4 h4 = *(const uint4*)arow_h;
        uint4 l4 = *(const uint4*)arow_l;
        *(uint4*)&sm->hi[0][srow][scolg * 4] = h4;
        *(uint4*)&sm->lo[0][srow][scolg * 4] = l4;
    }
    __syncthreads();

    for (int c = 0; c < nch; c++) {
        const int buf = c & 1;
        uint32_t bh[4][2], bl[4][2];
        const __nv_bfloat16* whc = wh + c * 64;
        const __nv_bfloat16* wlc = wl + c * 64;
#pragma unroll
        for (int ks = 0; ks < 4; ks++) {
            bh[ks][0] = *(const uint32_t*)(whc + ks * 16 + 2 * tq);
            bh[ks][1] = *(const uint32_t*)(whc + ks * 16 + 2 * tq + 8);
            bl[ks][0] = *(const uint32_t*)(wlc + ks * 16 + 2 * tq);
            bl[ks][1] = *(const uint32_t*)(wlc + ks * 16 + 2 * tq + 8);
        }
#pragma unroll
        for (int ks = 0; ks < 4; ks++) {
            const int p0 = ks * 8 + tq, p1 = p0 + 4;
            {   // m-tile 0 (rows 0-15)
                uint32_t ah0 = sm->hi[buf][g][p0],      ah1 = sm->hi[buf][g + 8][p0];
                uint32_t ah2 = sm->hi[buf][g][p1],      ah3 = sm->hi[buf][g + 8][p1];
                uint32_t al0 = sm->lo[buf][g][p0],      al1 = sm->lo[buf][g + 8][p0];
                uint32_t al2 = sm->lo[buf][g][p1],      al3 = sm->lo[buf][g + 8][p1];
                mma_bf16(d0, ah0, ah1, ah2, ah3, bh[ks][0], bh[ks][1]);
                mma_bf16(d0, ah0, ah1, ah2, ah3, bl[ks][0], bl[ks][1]);
                mma_bf16(d0, al0, al1, al2, al3, bh[ks][0], bh[ks][1]);
            }
            {   // m-tile 1 (rows 16-31)
                uint32_t ah0 = sm->hi[buf][16 + g][p0], ah1 = sm->hi[buf][24 + g][p0];
                uint32_t ah2 = sm->hi[buf][16 + g][p1], ah3 = sm->hi[buf][24 + g][p1];
                uint32_t al0 = sm->lo[buf][16 + g][p0], al1 = sm->lo[buf][24 + g][p0];
                uint32_t al2 = sm->lo[buf][16 + g][p1], al3 = sm->lo[buf][24 + g][p1];
                mma_bf16(d1, ah0, ah1, ah2, ah3, bh[ks][0], bh[ks][1]);
                mma_bf16(d1, ah0, ah1, ah2, ah3, bl[ks][0], bl[ks][1]);
                mma_bf16(d1, al0, al1, al2, al3, bh[ks][0], bh[ks][1]);
            }
        }
        if (c + 1 < nch) {
            uint4 h4 = *(const uint4*)(arow_h + (c + 1) * 32);
            uint4 l4 = *(const uint4*)(arow_l + (c + 1) * 32);
            __syncthreads();
            const int nb = buf ^ 1;
            *(uint4*)&sm->hi[nb][srow][scolg * 4] = h4;
            *(uint4*)&sm->lo[nb][srow][scolg * 4] = l4;
            __syncthreads();
        }
    }

    // epilogue
    const int nc = n0 + wid * 8 + 2 * tq;
    float bx = 0.f, by = 0.f;
    if (bias) { float2 bv = *(const float2*)(bias + nc); bx = bv.x; by = bv.y; }
    float v00 = d0[0] + bx, v01 = d0[1] + by;   // row g
    float v10 = d0[2] + bx, v11 = d0[3] + by;   // row g+8
    float v20 = d1[0] + bx, v21 = d1[1] + by;   // row 16+g
    float v30 = d1[2] + bx, v31 = d1[3] + by;   // row 24+g
    float2 r;
    r.x = v00; r.y = v01; *(float2*)(out + (long long)g * outStride + nc) = r;
    r.x = v10; r.y = v11; *(float2*)(out + (long long)(g + 8) * outStride + nc) = r;
    r.x = v20; r.y = v21; *(float2*)(out + (long long)(16 + g) * outStride + nc) = r;
    r.x = v30; r.y = v31; *(float2*)(out + (long long)(24 + g) * outStride + nc) = r;

    if (amax) {   // fused argmax partial
        __shared__ unsigned long long wmax[8][32];
        float v[4]  = {v00, v10, v20, v30};
        float w2[4] = {v01, v11, v21, v31};
        int rows[4] = {g, g + 8, 16 + g, 24 + g};
#pragma unroll
        for (int r4 = 0; r4 < 4; r4++) {
            float mv = v[r4]; int mi = nc;
            if (w2[r4] > mv) { mv = w2[r4]; mi = nc + 1; }
            unsigned long long p = pack_key(mv, mi);
            p = umax64(p, __shfl_xor_sync(0xffffffffu, p, 1));
            p = umax64(p, __shfl_xor_sync(0xffffffffu, p, 2));
            if (tq == 0) wmax[wid][rows[r4]] = p;
        }
        __syncthreads();
        if (tid < 32) {
            unsigned long long p = wmax[0][tid];
#pragma unroll
            for (int w8 = 1; w8 < 8; w8++) p = umax64(p, wmax[w8][tid]);
            atomicMax(&amax[tid], p);   // no return use -> REDG
        }
    }
}

// ---------------- GEMM wrappers ----------------
__global__ __launch_bounds__(256) void gemm_encproj_mma(const float* __restrict__ bias) {
    __shared__ SmemA sm;
    gemm_core(&sm, g_wenc_hi, g_wenc_lo, HH,
              (const uint32_t*)g_ehi + (long long)blockIdx.y * 16 * HH,
              (const uint32_t*)g_elo + (long long)blockIdx.y * 16 * HH, HH / 2,
              bias, g_enc_proj + (long long)blockIdx.y * 32 * HH, HH, HH,
              blockIdx.x * 64, nullptr);
}

__global__ __launch_bounds__(256) void gemm_fc_mma(const float* __restrict__ bias,
                                                   float* __restrict__ outp) {
    __shared__ SmemA sm;
    gemm_core(&sm, g_wfc_hi, g_wfc_lo, HH,
              (const uint32_t*)(g_hhi + BB * HH), (const uint32_t*)(g_hlo + BB * HH), HH / 2,
              bias, outp, (long long)TT * VV, HH, blockIdx.x * 64, g_amax);
}

// grid = 256: part 0,1 = ih k-halves; part 2,3 = hh k-halves -> gp0..gp3
__global__ __launch_bounds__(256) void gemm_gates_mma(int layer,
                                                      const float* __restrict__ b_ih,
                                                      const float* __restrict__ b_hh) {
    __shared__ SmemA sm;
    const int part = blockIdx.x >> 6;
    const int n0 = (blockIdx.x & 63) * 64;
    const __nv_bfloat16 *Whi, *Wlo;
    const uint32_t *Ahi, *Alo;
    const float* bias = nullptr;
    float* out;
    int K, wS, aS;
    if (layer == 0) {
        if (part < 2) {   // x @ W_ih0 (E=512 split in 2)
            K = 256; wS = EE; aS = EE / 2;
            Whi = g_wih0_hi + part * 256; Wlo = g_wih0_lo + part * 256;
            Ahi = (const uint32_t*)g_xhi + part * 128;
            Alo = (const uint32_t*)g_xlo + part * 128;
            bias = (part == 0) ? b_ih : nullptr;
            out = (part == 0) ? g_gp0 : g_gp1;
        } else {          // h0 @ W_hh0 (H=1024 split in 2)
            int kh = part - 2;
            K = 512; wS = HH; aS = HH / 2;
            Whi = g_whh0_hi + kh * 512; Wlo = g_whh0_lo + kh * 512;
            Ahi = (const uint32_t*)g_hhi + kh * 256;
            Alo = (const uint32_t*)g_hlo + kh * 256;
            bias = (kh == 0) ? b_hh : nullptr;
            out = (kh == 0) ? g_gp2 : g_gp3;
        }
    } else {
        if (part < 2) {   // h0 @ W_ih1
            K = 512; wS = HH; aS = HH / 2;
            Whi = g_wih1_hi + part * 512; Wlo = g_wih1_lo + part * 512;
            Ahi = (const uint32_t*)g_hhi + part * 256;
            Alo = (const uint32_t*)g_hlo + part * 256;
            bias = (part == 0) ? b_ih : nullptr;
            out = (part == 0) ? g_gp0 : g_gp1;
        } else {          // h1 @ W_hh1
            int kh = part - 2;
            K = 512; wS = HH; aS = HH / 2;
            Whi = g_whh1_hi + kh * 512; Wlo = g_whh1_lo + kh * 512;
            Ahi = (const uint32_t*)(g_hhi + BB * HH) + kh * 256;
            Alo = (const uint32_t*)(g_hlo + BB * HH) + kh * 256;
            bias = (kh == 0) ? b_hh : nullptr;
            out = (kh == 0) ? g_gp2 : g_gp3;
        }
    }
    gemm_core(&sm, Whi, Wlo, wS, Ahi, Alo, aS, bias, out, G4H, K, n0, nullptr);
}

// ---------------- q = h1 @ W_att_dec^T + b  (warp per (b,n)) ----------------
__global__ void q_kernel(const float* __restrict__ Wd, const float* __restrict__ bd) {
    int gw = blockIdx.x * 8 + (threadIdx.x >> 5);
    int lane = threadIdx.x & 31;
    int n = gw & (HH - 1), b = gw >> 10;
    const float* w = Wd + (long long)n * HH;
    const float* a = g_h + BB * HH + b * HH;   // h1
    float s = 0.0f;
#pragma unroll
    for (int it = 0; it < 8; it++) {
        int k = it * 128 + lane * 4;
        float4 wv = *(const float4*)(w + k);
        float4 av = *(const float4*)(a + k);
        s += wv.x * av.x + wv.y * av.y + wv.z * av.z + wv.w * av.w;
    }
#pragma unroll
    for (int o = 16; o; o >>= 1) s += __shfl_xor_sync(0xffffffffu, s, o);
    if (!lane) g_q[b * HH + n] = s + bd[n];
}

// ---------------- energy: e[b,l] = sum_h tanh(enc_proj + q) * v_att ----------------
__global__ void energy_kernel(const float* __restrict__ v_att) {
    __shared__ float qs[HH];
    __shared__ float vs[HH];
    int b = blockIdx.x >> 6;
    int l0 = (blockIdx.x & 63) << 3;
    {
        int i = threadIdx.x * 4;
        *(float4*)&qs[i] = *(const float4*)&g_q[b * HH + i];
        *(float4*)&vs[i] = *(const float4*)&v_att[i];
    }
    __syncthreads();
    int w = threadIdx.x >> 5, lane = threadIdx.x & 31;
    int l = l0 + w;
    const float* ep = g_enc_proj + (long long)(b * LL + l) * HH;
    float s = 0.0f;
#pragma unroll
    for (int it = 0; it < 8; it++) {
        int k = it * 128 + lane * 4;
        float4 e4 = *(const float4*)(ep + k);
        s += fast_tanh(e4.x + qs[k + 0]) * vs[k + 0];
        s += fast_tanh(e4.y + qs[k + 1]) * vs[k + 1];
        s += fast_tanh(e4.z + qs[k + 2]) * vs[k + 2];
        s += fast_tanh(e4.w + qs[k + 3]) * vs[k + 3];
    }
#pragma unroll
    for (int o = 16; o; o >>= 1) s += __shfl_xor_sync(0xffffffffu, s, o);
    if (!lane) g_e[b * LL + l] = s;
}

// ---------------- fused softmax + ctx:  ctx[b,h] = sum_l softmax(e)[l] * enc[b,l,h] --------
__global__ __launch_bounds__(128) void ctx_kernel(const float* __restrict__ enc) {
    __shared__ float al[LL];
    __shared__ float redm[4], reds[4];
    int b = blockIdx.x >> 3, hc = blockIdx.x & 7;
    int tid = threadIdx.x;
    float4 ev = *(const float4*)(g_e + b * LL + tid * 4);
    float m = fmaxf(fmaxf(ev.x, ev.y), fmaxf(ev.z, ev.w));
#pragma unroll
    for (int o = 16; o; o >>= 1) m = fmaxf(m, __shfl_xor_sync(0xffffffffu, m, o));
    if ((tid & 31) == 0) redm[tid >> 5] = m;
    __syncthreads();
    m = fmaxf(fmaxf(redm[0], redm[1]), fmaxf(redm[2], redm[3]));
    float e0 = __expf(ev.x - m), e1 = __expf(ev.y - m);
    float e2 = __expf(ev.z - m), e3 = __expf(ev.w - m);
    float s = e0 + e1 + e2 + e3;
#pragma unroll
    for (int o = 16; o; o >>= 1) s += __shfl_xor_sync(0xffffffffu, s, o);
    if ((tid & 31) == 0) reds[tid >> 5] = s;
    __syncthreads();
    s = reds[0] + reds[1] + reds[2] + reds[3];
    float inv = 1.0f / s;
    al[tid * 4 + 0] = e0 * inv; al[tid * 4 + 1] = e1 * inv;
    al[tid * 4 + 2] = e2 * inv; al[tid * 4 + 3] = e3 * inv;
    __syncthreads();
    int h = hc * 128 + tid;
    const float* ep = enc + (long long)b * LL * HH + h;
    float acc = 0.0f;
#pragma unroll 8
    for (int l = 0; l < LL; l++) acc += al[l] * ep[(long long)l * HH];
    g_ctx[b * HH + h] = acc;
}

// ---------------- x = concat(emb[tok], ctx) @ W_in^T + b_in  (bf16 hi/lo out) --------
__global__ void x_kernel(const float* __restrict__ Win, const float* __restrict__ bin,
                         const float* __restrict__ emb) {
    int gw = blockIdx.x * 8 + (threadIdx.x >> 5);
    int lane = threadIdx.x & 31;
    int n = gw & (EE - 1), b = gw >> 9;
    const float* w = Win + (long long)n * (EE + HH);
    const float* er = emb + (long long)g_tok[b] * EE;
    const float* cr = g_ctx + b * HH;
    float s = 0.0f;
#pragma unroll
    for (int it = 0; it < 4; it++) {
        int k = it * 128 + lane * 4;
        float4 wv = *(const float4*)(w + k);
        float4 av = *(const float4*)(er + k);
        s += wv.x * av.x + wv.y * av.y + wv.z * av.z + wv.w * av.w;
    }
#pragma unroll
    for (int it = 0; it < 8; it++) {
        int k = it * 128 + lane * 4;
        float4 wv = *(const float4*)(w + EE + k);
        float4 av = *(const float4*)(cr + k);
        s += wv.x * av.x + wv.y * av.y + wv.z * av.z + wv.w * av.w;
    }
#pragma unroll
    for (int o = 16; o; o >>= 1) s += __shfl_xor_sync(0xffffffffu, s, o);
    if (!lane) {
        s += bin[n];
        __nv_bfloat16 hi = __float2bfloat16(s);
        g_xhi[b * EE + n] = hi;
        g_xlo[b * EE + n] = __float2bfloat16(s - __bfloat162float(hi));
    }
}

// ---------------- LSTM elementwise cell update (4 partials; emits bf16 h) -----------
__global__ void lstm_elt(int layer) {
    int id = blockIdx.x * blockDim.x + threadIdx.x;   // 32768
    int b = id >> 10, hh = id & 1023;
    int o0 = b * G4H + hh;
    float gi = g_gp0[o0]        + g_gp1[o0]        + g_gp2[o0]        + g_gp3[o0];
    float gf = g_gp0[o0 + 1024] + g_gp1[o0 + 1024] + g_gp2[o0 + 1024] + g_gp3[o0 + 1024];
    float gg = g_gp0[o0 + 2048] + g_gp1[o0 + 2048] + g_gp2[o0 + 2048] + g_gp3[o0 + 2048];
    float go = g_gp0[o0 + 3072] + g_gp1[o0 + 3072] + g_gp2[o0 + 3072] + g_gp3[o0 + 3072];
    int hidx = layer * BB * HH + b * HH + hh;
    float cn = acc_sig(gf) * g_c[hidx] + acc_sig(gi) * tanhf(gg);
    g_c[hidx] = cn;
    float hn = acc_sig(go) * tanhf(cn);
    g_h[hidx] = hn;
    __nv_bfloat16 hb = __float2bfloat16(hn);
    g_hhi[hidx] = hb;
    g_hlo[hidx] = __float2bfloat16(hn - __bfloat162float(hb));
    if (layer == 1 && blockIdx.x == 0 && threadIdx.x < BB)
        g_amax[threadIdx.x] = 0ull;   // reset argmax accumulators before fc
}

// ---------------- finalize token from packed argmax ----------------
__global__ void tok_finalize(float* __restrict__ out, int t) {
    int b = threadIdx.x;
    if (b < BB) {
        unsigned long long p = g_amax[b];
        int idx = VV - (int)(unsigned int)(p & 0xFFFFFFFFu);
        g_tok[b] = idx;
        out[(long long)BB * TT * VV + b * TT + t] = (float)idx;
    }
}

// ---------------- launch ----------------
extern "C" void kernel_launch(void* const* d_in, const int* in_sizes, int n_in,
                              void* d_out, int out_size) {
    const float* enc_output = (const float*)d_in[0];
    const int*   trg        = (const int*)d_in[1];     // int32 (JAX x64 disabled)
    const float* emb        = (const float*)d_in[2];
    const float* W_att_enc  = (const float*)d_in[3];
    const float* b_att_enc  = (const float*)d_in[4];
    const float* W_att_dec  = (const float*)d_in[5];
    const float* b_att_dec  = (const float*)d_in[6];
    const float* v_att      = (const float*)d_in[7];
    const float* W_in       = (const float*)d_in[8];
    const float* b_in       = (const float*)d_in[9];
    const float* W_ih0      = (const float*)d_in[10];
    const float* W_hh0      = (const float*)d_in[11];
    const float* b_ih0      = (const float*)d_in[12];
    const float* b_hh0      = (const float*)d_in[13];
    const float* W_ih1      = (const float*)d_in[14];
    const float* W_hh1      = (const float*)d_in[15];
    const float* b_ih1      = (const float*)d_in[16];
    const float* b_hh1      = (const float*)d_in[17];
    const float* W_fc       = (const float*)d_in[18];
    const float* b_fc       = (const float*)d_in[19];
    float* out = (float*)d_out;

    init_kernel<<<(BB * VV + 255) / 256, 256>>>(trg, out);

    void *enc_hi, *enc_lo, *ih0_hi, *ih0_lo, *hh0_hi, *hh0_lo;
    void *ih1_hi, *ih1_lo, *hh1_hi, *hh1_lo, *fc_hi, *fc_lo, *e_hi, *e_lo;
    cudaGetSymbolAddress(&enc_hi, g_wenc_hi); cudaGetSymbolAddress(&enc_lo, g_wenc_lo);
    cudaGetSymbolAddress(&ih0_hi, g_wih0_hi); cudaGetSymbolAddress(&ih0_lo, g_wih0_lo);
    cudaGetSymbolAddress(&hh0_hi, g_whh0_hi); cudaGetSymbolAddress(&hh0_lo, g_whh0_lo);
    cudaGetSymbolAddress(&ih1_hi, g_wih1_hi); cudaGetSymbolAddress(&ih1_lo, g_wih1_lo);
    cudaGetSymbolAddress(&hh1_hi, g_whh1_hi); cudaGetSymbolAddress(&hh1_lo, g_whh1_lo);
    cudaGetSymbolAddress(&fc_hi,  g_wfc_hi);  cudaGetSymbolAddress(&fc_lo,  g_wfc_lo);
    cudaGetSymbolAddress(&e_hi,   g_ehi);     cudaGetSymbolAddress(&e_lo,   g_elo);

    {
        long long n;
        n = (long long)HH * HH / 4;
        split_w_kernel<<<(int)((n + 255) / 256), 256>>>(W_att_enc, (__nv_bfloat16*)enc_hi, (__nv_bfloat16*)enc_lo, (int)n);
        n = (long long)G4H * EE / 4;
        split_w_kernel<<<(int)((n + 255) / 256), 256>>>(W_ih0, (__nv_bfloat16*)ih0_hi, (__nv_bfloat16*)ih0_lo, (int)n);
        n = (long long)G4H * HH / 4;
        split_w_kernel<<<(int)((n + 255) / 256), 256>>>(W_hh0, (__nv_bfloat16*)hh0_hi, (__nv_bfloat16*)hh0_lo, (int)n);
        split_w_kernel<<<(int)((n + 255) / 256), 256>>>(W_ih1, (__nv_bfloat16*)ih1_hi, (__nv_bfloat16*)ih1_lo, (int)n);
        split_w_kernel<<<(int)((n + 255) / 256), 256>>>(W_hh1, (__nv_bfloat16*)hh1_hi, (__nv_bfloat16*)hh1_lo, (int)n);
        n = (long long)VV * HH / 4;
        split_w_kernel<<<(int)((n + 255) / 256), 256>>>(W_fc, (__nv_bfloat16*)fc_hi, (__nv_bfloat16*)fc_lo, (int)n);
        n = (long long)BB * LL * HH / 4;
        split_w_kernel<<<(int)((n + 255) / 256), 256>>>(enc_output, (__nv_bfloat16*)e_hi, (__nv_bfloat16*)e_lo, (int)n);
    }

    // enc_proj = enc_output @ W_att_enc^T + b_att_enc   [B*L, H]
    gemm_encproj_mma<<<dim3(HH / 64, (BB * LL) / 32), 256>>>(b_att_enc);

    for (int t = 1; t < TT; t++) {
        q_kernel<<<(BB * HH / 8), 256>>>(W_att_dec, b_att_dec);
        energy_kernel<<<BB * (LL / 8), 256>>>(v_att);
        ctx_kernel<<<BB * 8, 128>>>(enc_output);
        x_kernel<<<(BB * EE / 8), 256>>>(W_in, b_in, emb);

        gemm_gates_mma<<<256, 256>>>(0, b_ih0, b_hh0);
        lstm_elt<<<BB * HH / 256, 256>>>(0);

        gemm_gates_mma<<<256, 256>>>(1, b_ih1, b_hh1);
        lstm_elt<<<BB * HH / 256, 256>>>(1);

        gemm_fc_mma<<<VV / 64, 256>>>(b_fc, out + (long long)t * VV);
        tok_finalize<<<1, 32>>>(out, t);
    }
}

// round 6
// speedup vs baseline: 3.0643x; 1.5408x over previous
#include <cuda_runtime.h>
#include <cuda_bf16.h>
#include <stdint.h>

#define BB 32
#define LL 512
#define EE 512
#define HH 1024
#define VV 32000
#define TT 64
#define G4H 4096
#define KX 1536   // E + H (x GEMM K)

// ---------------- scratch (device globals; no allocation allowed) ----------------
__device__ float g_enc_proj[BB * LL * HH];   // 67 MB
__device__ float g_c[2 * BB * HH];
__device__ float g_e[BB * LL];
__device__ float g_qp[4 * BB * HH];          // q split-K partials
__device__ float g_ctxp4[4 * BB * HH];       // ctx l-split partials
__device__ float g_xp[4 * BB * EE];          // x split-K partials
__device__ float g_gp0[BB * G4H];
__device__ float g_gp1[BB * G4H];
__device__ float g_gp2[BB * G4H];
__device__ float g_gp3[BB * G4H];
__device__ int   g_tok[BB];
__device__ unsigned long long g_amax[BB];

// frag-interleaved packed bf16 weights (hi/lo)
__device__ __nv_bfloat16 g_wenc_hi[HH * HH],  g_wenc_lo[HH * HH];
__device__ __nv_bfloat16 g_wdec_hi[HH * HH],  g_wdec_lo[HH * HH];
__device__ __nv_bfloat16 g_win_hi[EE * KX],   g_win_lo[EE * KX];
__device__ __nv_bfloat16 g_wih0_hi[G4H * EE], g_wih0_lo[G4H * EE];
__device__ __nv_bfloat16 g_whh0_hi[G4H * HH], g_whh0_lo[G4H * HH];
__device__ __nv_bfloat16 g_wih1_hi[G4H * HH], g_wih1_lo[G4H * HH];
__device__ __nv_bfloat16 g_whh1_hi[G4H * HH], g_whh1_lo[G4H * HH];
__device__ __nv_bfloat16 g_wfc_hi[(long long)VV * HH], g_wfc_lo[(long long)VV * HH];
// linear bf16 hi/lo activations (A-side)
__device__ __nv_bfloat16 g_ehi[BB * LL * HH], g_elo[BB * LL * HH];
__device__ __nv_bfloat16 g_xinhi[BB * KX],    g_xinlo[BB * KX];      // concat(emb,ctx)
__device__ __nv_bfloat16 g_xhi[BB * EE],      g_xlo[BB * EE];
__device__ __nv_bfloat16 g_hhi[2 * BB * HH],  g_hlo[2 * BB * HH];

__device__ __forceinline__ float acc_sig(float x) { return 1.0f / (1.0f + expf(-x)); }
__device__ __forceinline__ float fast_tanh(float x) {
    float xc = fminf(fmaxf(x, -15.0f), 15.0f);
    float t = __expf(2.0f * xc);
    return __fdividef(t - 1.0f, t + 1.0f);
}
__device__ __forceinline__ unsigned long long pack_key(float f, int idx) {
    unsigned int b = __float_as_uint(f);
    b = (b & 0x80000000u) ? ~b : (b | 0x80000000u);
    return ((unsigned long long)b << 32) | (unsigned int)(VV - idx);
}
__device__ __forceinline__ unsigned long long umax64(unsigned long long a, unsigned long long b) {
    return a > b ? a : b;
}

// ---------------- init ----------------
__global__ void init_kernel(const int* __restrict__ trg, float* __restrict__ out) {
    int gid = blockIdx.x * blockDim.x + threadIdx.x;
    if (gid < BB * VV) {
        int b = gid / VV, v = gid - b * VV;
        out[(long long)b * TT * VV + v] = 0.0f;
    }
    if (gid < 2 * BB * HH) {
        g_c[gid] = 0.0f;
        g_hhi[gid] = __float2bfloat16(0.0f);
        g_hlo[gid] = __float2bfloat16(0.0f);
    }
    if (gid < BB) {
        g_tok[gid] = trg[gid * TT];
        out[(long long)BB * TT * VV + gid * TT] = 1.0f;
    }
}

// ---------------- linear split (activations / enc_output) ----------------
__global__ void split_w_kernel(const float* __restrict__ src,
                               __nv_bfloat16* __restrict__ hi,
                               __nv_bfloat16* __restrict__ lo, int n4) {
    int i = blockIdx.x * 256 + threadIdx.x;
    if (i >= n4) return;
    long long idx = (long long)i * 4;
    float4 v = *(const float4*)(src + idx);
    float f[4] = {v.x, v.y, v.z, v.w};
    __nv_bfloat16 h[4], l[4];
#pragma unroll
    for (int j = 0; j < 4; j++) {
        h[j] = __float2bfloat16(f[j]);
        l[j] = __float2bfloat16(f[j] - __bfloat162float(h[j]));
    }
    __nv_bfloat162 hp0; hp0.x = h[0]; hp0.y = h[1];
    __nv_bfloat162 hp1; hp1.x = h[2]; hp1.y = h[3];
    __nv_bfloat162 lp0; lp0.x = l[0]; lp0.y = l[1];
    __nv_bfloat162 lp1; lp1.x = l[2]; lp1.y = l[3];
    *(uint32_t*)(hi + idx)     = *(uint32_t*)&hp0;
    *(uint32_t*)(hi + idx + 2) = *(uint32_t*)&hp1;
    *(uint32_t*)(lo + idx)     = *(uint32_t*)&lp0;
    *(uint32_t*)(lo + idx + 2) = *(uint32_t*)&lp1;
}

// ---------------- frag-interleaved weight pack:  W fp32 [N][K] -> packed hi/lo ----------
// dest word = ((n>>3)*nch + c)*256 + ((n&7)*4 + tq)*8 + h*4 + ks
// where k = c*64 + ks*16 + h*8 + 2*tq  (word covers elems k, k+1)
__global__ void pack_w_kernel(const float* __restrict__ src,
                              __nv_bfloat16* __restrict__ hi,
                              __nv_bfloat16* __restrict__ lo,
                              int N, int K) {
    long long w = (long long)blockIdx.x * 256 + threadIdx.x;
    long long total = (long long)N * (K / 2);
    if (w >= total) return;
    int kw = K / 2;
    int n = (int)(w / kw);
    int k = (int)(w % kw) * 2;
    int c = k >> 6, r = k & 63;
    int ks = r >> 4, rr = r & 15;
    int h = rr >> 3, tq = (rr >> 1) & 3;
    int nch = K >> 6;
    long long dest = ((long long)(n >> 3) * nch + c) * 256 + ((n & 7) * 4 + tq) * 8 + h * 4 + ks;
    float f0 = src[(long long)n * K + k];
    float f1 = src[(long long)n * K + k + 1];
    __nv_bfloat16 h0 = __float2bfloat16(f0), h1 = __float2bfloat16(f1);
    __nv_bfloat162 hp; hp.x = h0; hp.y = h1;
    __nv_bfloat162 lp;
    lp.x = __float2bfloat16(f0 - __bfloat162float(h0));
    lp.y = __float2bfloat16(f1 - __bfloat162float(h1));
    ((uint32_t*)hi)[dest] = *(uint32_t*)&hp;
    ((uint32_t*)lo)[dest] = *(uint32_t*)&lp;
}

// ---------------- bf16-split MMA GEMM core ----------
__device__ __forceinline__ void mma_bf16(float* d, uint32_t a0, uint32_t a1, uint32_t a2,
                                         uint32_t a3, uint32_t b0, uint32_t b1) {
    asm volatile(
        "mma.sync.aligned.m16n8k16.row.col.f32.bf16.bf16.f32 "
        "{%0,%1,%2,%3}, {%4,%5,%6,%7}, {%8,%9}, {%0,%1,%2,%3};"
        : "+f"(d[0]), "+f"(d[1]), "+f"(d[2]), "+f"(d[3])
        : "r"(a0), "r"(a1), "r"(a2), "r"(a3), "r"(b0), "r"(b1));
}

struct SmemA {
    uint32_t hi[2][32][36];
    uint32_t lo[2][32][36];
};

__device__ __forceinline__ void gemm_core(
    SmemA* sm,
    const uint4* __restrict__ pWhi, const uint4* __restrict__ pWlo,
    int nchFull, int c0, int ncnt,
    const uint32_t* __restrict__ Ahi, const uint32_t* __restrict__ Alo, int aStrideW,
    const float* __restrict__ bias,
    float* __restrict__ out, long long outStride,
    int n0, unsigned long long* amax)
{
    const int tid = threadIdx.x;
    const int wid = tid >> 5, lane = tid & 31;
    const int g = lane >> 2, tq = lane & 3;

    const long long ntile = (n0 >> 3) + wid;
    const uint4* pbh = pWhi + (ntile * nchFull + c0) * 64 + lane * 2;
    const uint4* pbl = pWlo + (ntile * nchFull + c0) * 64 + lane * 2;

    float d0[4] = {0.f, 0.f, 0.f, 0.f};
    float d1[4] = {0.f, 0.f, 0.f, 0.f};

    const int srow = tid >> 3, scolg = tid & 7;
    const uint32_t* arow_h = Ahi + (long long)srow * aStrideW + scolg * 4;
    const uint32_t* arow_l = Alo + (long long)srow * aStrideW + scolg * 4;

    {   // stage A chunk 0
        uint4 h4 = *(const uint4*)arow_h;
        uint4 l4 = *(const uint4*)arow_l;
        *(uint4*)&sm->hi[0][srow][scolg * 4] = h4;
        *(uint4*)&sm->lo[0][srow][scolg * 4] = l4;
    }
    // B regs chunk 0
    uint4 cf0h = pbh[0], cf1h = pbh[1];
    uint4 cf0l = pbl[0], cf1l = pbl[1];
    __syncthreads();

    for (int c = 0; c < ncnt; c++) {
        const int buf = c & 1;
        const bool more = (c + 1 < ncnt);
        uint4 nf0h, nf1h, nf0l, nf1l, nh4, nl4;
        if (more) {
            nf0h = pbh[(c + 1) * 64];     nf1h = pbh[(c + 1) * 64 + 1];
            nf0l = pbl[(c + 1) * 64];     nf1l = pbl[(c + 1) * 64 + 1];
            nh4 = *(const uint4*)(arow_h + (c + 1) * 32);
            nl4 = *(const uint4*)(arow_l + (c + 1) * 32);
        }
        uint32_t bh0[4] = {cf0h.x, cf0h.y, cf0h.z, cf0h.w};
        uint32_t bh1[4] = {cf1h.x, cf1h.y, cf1h.z, cf1h.w};
        uint32_t bl0[4] = {cf0l.x, cf0l.y, cf0l.z, cf0l.w};
        uint32_t bl1[4] = {cf1l.x, cf1l.y, cf1l.z, cf1l.w};
#pragma unroll
        for (int ks = 0; ks < 4; ks++) {
            const int p0 = ks * 8 + tq, p1 = p0 + 4;
            {   // m-tile 0
                uint32_t ah0 = sm->hi[buf][g][p0],      ah1 = sm->hi[buf][g + 8][p0];
                uint32_t ah2 = sm->hi[buf][g][p1],      ah3 = sm->hi[buf][g + 8][p1];
                uint32_t al0 = sm->lo[buf][g][p0],      al1 = sm->lo[buf][g + 8][p0];
                uint32_t al2 = sm->lo[buf][g][p1],      al3 = sm->lo[buf][g + 8][p1];
                mma_bf16(d0, ah0, ah1, ah2, ah3, bh0[ks], bh1[ks]);
                mma_bf16(d0, ah0, ah1, ah2, ah3, bl0[ks], bl1[ks]);
                mma_bf16(d0, al0, al1, al2, al3, bh0[ks], bh1[ks]);
            }
            {   // m-tile 1
                uint32_t ah0 = sm->hi[buf][16 + g][p0], ah1 = sm->hi[buf][24 + g][p0];
                uint32_t ah2 = sm->hi[buf][16 + g][p1], ah3 = sm->hi[buf][24 + g][p1];
                uint32_t al0 = sm->lo[buf][16 + g][p0], al1 = sm->lo[buf][24 + g][p0];
                uint32_t al2 = sm->lo[buf][16 + g][p1], al3 = sm->lo[buf][24 + g][p1];
                mma_bf16(d1, ah0, ah1, ah2, ah3, bh0[ks], bh1[ks]);
                mma_bf16(d1, ah0, ah1, ah2, ah3, bl0[ks], bl1[ks]);
                mma_bf16(d1, al0, al1, al2, al3, bh0[ks], bh1[ks]);
            }
        }
        if (more) {
            __syncthreads();
            const int nb = buf ^ 1;
            *(uint4*)&sm->hi[nb][srow][scolg * 4] = nh4;
            *(uint4*)&sm->lo[nb][srow][scolg * 4] = nl4;
            __syncthreads();
            cf0h = nf0h; cf1h = nf1h; cf0l = nf0l; cf1l = nf1l;
        }
    }

    // epilogue
    const int nc = n0 + wid * 8 + 2 * tq;
    float bx = 0.f, by = 0.f;
    if (bias) { float2 bv = *(const float2*)(bias + nc); bx = bv.x; by = bv.y; }
    float v00 = d0[0] + bx, v01 = d0[1] + by;
    float v10 = d0[2] + bx, v11 = d0[3] + by;
    float v20 = d1[0] + bx, v21 = d1[1] + by;
    float v30 = d1[2] + bx, v31 = d1[3] + by;
    float2 r;
    r.x = v00; r.y = v01; *(float2*)(out + (long long)g * outStride + nc) = r;
    r.x = v10; r.y = v11; *(float2*)(out + (long long)(g + 8) * outStride + nc) = r;
    r.x = v20; r.y = v21; *(float2*)(out + (long long)(16 + g) * outStride + nc) = r;
    r.x = v30; r.y = v31; *(float2*)(out + (long long)(24 + g) * outStride + nc) = r;

    if (amax) {
        __shared__ unsigned long long wmax[8][32];
        float v[4]  = {v00, v10, v20, v30};
        float w2[4] = {v01, v11, v21, v31};
        int rows[4] = {g, g + 8, 16 + g, 24 + g};
#pragma unroll
        for (int r4 = 0; r4 < 4; r4++) {
            float mv = v[r4]; int mi = nc;
            if (w2[r4] > mv) { mv = w2[r4]; mi = nc + 1; }
            unsigned long long p = pack_key(mv, mi);
            p = umax64(p, __shfl_xor_sync(0xffffffffu, p, 1));
            p = umax64(p, __shfl_xor_sync(0xffffffffu, p, 2));
            if (tq == 0) wmax[wid][rows[r4]] = p;
        }
        __syncthreads();
        if (tid < 32) {
            unsigned long long p = wmax[0][tid];
#pragma unroll
            for (int w8 = 1; w8 < 8; w8++) p = umax64(p, wmax[w8][tid]);
            atomicMax(&amax[tid], p);
        }
    }
}

// ---------------- GEMM wrappers ----------------
__global__ __launch_bounds__(256) void gemm_encproj_mma(const float* __restrict__ bias) {
    __shared__ SmemA sm;
    gemm_core(&sm, (const uint4*)g_wenc_hi, (const uint4*)g_wenc_lo, 16, 0, 16,
              (const uint32_t*)g_ehi + (long long)blockIdx.y * 16 * HH,
              (const uint32_t*)g_elo + (long long)blockIdx.y * 16 * HH, HH / 2,
              bias, g_enc_proj + (long long)blockIdx.y * 32 * HH, HH,
              blockIdx.x * 64, nullptr);
}

__global__ __launch_bounds__(256) void gemm_fc_mma(const float* __restrict__ bias,
                                                   float* __restrict__ outp) {
    __shared__ SmemA sm;
    gemm_core(&sm, (const uint4*)g_wfc_hi, (const uint4*)g_wfc_lo, 16, 0, 16,
              (const uint32_t*)(g_hhi + BB * HH), (const uint32_t*)(g_hlo + BB * HH), HH / 2,
              bias, outp, (long long)TT * VV, blockIdx.x * 64, g_amax);
}

// q = h1 @ W_att_dec^T  (split-K x4 partials, bias added in energy)
__global__ __launch_bounds__(256) void gemm_q_mma() {
    __shared__ SmemA sm;
    const int part = blockIdx.y;
    gemm_core(&sm, (const uint4*)g_wdec_hi, (const uint4*)g_wdec_lo, 16, part * 4, 4,
              (const uint32_t*)(g_hhi + BB * HH) + part * 128,
              (const uint32_t*)(g_hlo + BB * HH) + part * 128, HH / 2,
              nullptr, g_qp + (long long)part * BB * HH, HH,
              blockIdx.x * 64, nullptr);
}

// x = concat(emb,ctx) @ W_in^T  (split-K x4 partials, bias added in combine)
__global__ __launch_bounds__(256) void gemm_x_mma() {
    __shared__ SmemA sm;
    const int part = blockIdx.y;
    gemm_core(&sm, (const uint4*)g_win_hi, (const uint4*)g_win_lo, 24, part * 6, 6,
              (const uint32_t*)g_xinhi + part * 192,
              (const uint32_t*)g_xinlo + part * 192, KX / 2,
              nullptr, g_xp + (long long)part * BB * EE, EE,
              blockIdx.x * 64, nullptr);
}

// gates: 4 parts -> gp0..gp3
__global__ __launch_bounds__(256) void gemm_gates_mma(int layer,
                                                      const float* __restrict__ b_ih,
                                                      const float* __restrict__ b_hh) {
    __shared__ SmemA sm;
    const int part = blockIdx.x >> 6;
    const int n0 = (blockIdx.x & 63) * 64;
    const uint4 *Whi, *Wlo;
    const uint32_t *Ahi, *Alo;
    const float* bias = nullptr;
    float* out;
    int nchFull, c0, ncnt, aS;
    if (layer == 0) {
        if (part < 2) {   // x @ W_ih0, K=512 split 2
            nchFull = 8; c0 = part * 4; ncnt = 4; aS = EE / 2;
            Whi = (const uint4*)g_wih0_hi; Wlo = (const uint4*)g_wih0_lo;
            Ahi = (const uint32_t*)g_xhi + part * 128;
            Alo = (const uint32_t*)g_xlo + part * 128;
            bias = (part == 0) ? b_ih : nullptr;
            out = (part == 0) ? g_gp0 : g_gp1;
        } else {          // h0 @ W_hh0, K=1024 split 2
            int kh = part - 2;
            nchFull = 16; c0 = kh * 8; ncnt = 8; aS = HH / 2;
            Whi = (const uint4*)g_whh0_hi; Wlo = (const uint4*)g_whh0_lo;
            Ahi = (const uint32_t*)g_hhi + kh * 256;
            Alo = (const uint32_t*)g_hlo + kh * 256;
            bias = (kh == 0) ? b_hh : nullptr;
            out = (kh == 0) ? g_gp2 : g_gp3;
        }
    } else {
        if (part < 2) {   // h0 @ W_ih1
            nchFull = 16; c0 = part * 8; ncnt = 8; aS = HH / 2;
            Whi = (const uint4*)g_wih1_hi; Wlo = (const uint4*)g_wih1_lo;
            Ahi = (const uint32_t*)g_hhi + part * 256;
            Alo = (const uint32_t*)g_hlo + part * 256;
            bias = (part == 0) ? b_ih : nullptr;
            out = (part == 0) ? g_gp0 : g_gp1;
        } else {          // h1 @ W_hh1
            int kh = part - 2;
            nchFull = 16; c0 = kh * 8; ncnt = 8; aS = HH / 2;
            Whi = (const uint4*)g_whh1_hi; Wlo = (const uint4*)g_whh1_lo;
            Ahi = (const uint32_t*)(g_hhi + BB * HH) + kh * 256;
            Alo = (const uint32_t*)(g_hlo + BB * HH) + kh * 256;
            bias = (kh == 0) ? b_hh : nullptr;
            out = (kh == 0) ? g_gp2 : g_gp3;
        }
    }
    gemm_core(&sm, Whi, Wlo, nchFull, c0, ncnt, Ahi, Alo, aS, bias, out, G4H, n0, nullptr);
}

// ---------------- energy: e[b,l] = sum_h tanh(enc_proj + q) * v_att  (sums q partials) ----
__global__ void energy_kernel(const float* __restrict__ v_att,
                              const float* __restrict__ bd) {
    __shared__ float qs[HH];
    __shared__ float vs[HH];
    int b = blockIdx.x >> 6;
    int l0 = (blockIdx.x & 63) << 3;
    {
        int i = threadIdx.x * 4;
        float4 q0 = *(const float4*)&g_qp[0 * BB * HH + b * HH + i];
        float4 q1 = *(const float4*)&g_qp[1 * BB * HH + b * HH + i];
        float4 q2 = *(const float4*)&g_qp[2 * BB * HH + b * HH + i];
        float4 q3 = *(const float4*)&g_qp[3 * BB * HH + b * HH + i];
        float4 bv = *(const float4*)&bd[i];
        float4 qv;
        qv.x = q0.x + q1.x + q2.x + q3.x + bv.x;
        qv.y = q0.y + q1.y + q2.y + q3.y + bv.y;
        qv.z = q0.z + q1.z + q2.z + q3.z + bv.z;
        qv.w = q0.w + q1.w + q2.w + q3.w + bv.w;
        *(float4*)&qs[i] = qv;
        *(float4*)&vs[i] = *(const float4*)&v_att[i];
    }
    __syncthreads();
    int w = threadIdx.x >> 5, lane = threadIdx.x & 31;
    int l = l0 + w;
    const float* ep = g_enc_proj + (long long)(b * LL + l) * HH;
    float s = 0.0f;
#pragma unroll
    for (int it = 0; it < 8; it++) {
        int k = it * 128 + lane * 4;
        float4 e4 = *(const float4*)(ep + k);
        s += fast_tanh(e4.x + qs[k + 0]) * vs[k + 0];
        s += fast_tanh(e4.y + qs[k + 1]) * vs[k + 1];
        s += fast_tanh(e4.z + qs[k + 2]) * vs[k + 2];
        s += fast_tanh(e4.w + qs[k + 3]) * vs[k + 3];
    }
#pragma unroll
    for (int o = 16; o; o >>= 1) s += __shfl_xor_sync(0xffffffffu, s, o);
    if (!lane) g_e[b * LL + l] = s;
}

// ---------------- ctx partials over l-ranges (softmax stats recomputed per block) -------
__global__ __launch_bounds__(128) void ctx_part_kernel(const float* __restrict__ enc) {
    __shared__ float al[LL];
    __shared__ float redm[4], reds[4];
    int hs = blockIdx.x, lp = blockIdx.y, b = blockIdx.z;
    int tid = threadIdx.x;
    float4 ev = *(const float4*)(g_e + b * LL + tid * 4);
    float m = fmaxf(fmaxf(ev.x, ev.y), fmaxf(ev.z, ev.w));
#pragma unroll
    for (int o = 16; o; o >>= 1) m = fmaxf(m, __shfl_xor_sync(0xffffffffu, m, o));
    if ((tid & 31) == 0) redm[tid >> 5] = m;
    __syncthreads();
    m = fmaxf(fmaxf(redm[0], redm[1]), fmaxf(redm[2], redm[3]));
    float e0 = __expf(ev.x - m), e1 = __expf(ev.y - m);
    float e2 = __expf(ev.z - m), e3 = __expf(ev.w - m);
    float s = e0 + e1 + e2 + e3;
#pragma unroll
    for (int o = 16; o; o >>= 1) s += __shfl_xor_sync(0xffffffffu, s, o);
    if ((tid & 31) == 0) reds[tid >> 5] = s;
    __syncthreads();
    s = reds[0] + reds[1] + reds[2] + reds[3];
    float inv = 1.0f / s;
    al[tid * 4 + 0] = e0 * inv; al[tid * 4 + 1] = e1 * inv;
    al[tid * 4 + 2] = e2 * inv; al[tid * 4 + 3] = e3 * inv;
    __syncthreads();
    int h = hs * 512 + tid * 4;
    const float* ep = enc + (long long)b * LL * HH + (long long)lp * 128 * HH + h;
    float4 acc = {0.f, 0.f, 0.f, 0.f};
#pragma unroll 4
    for (int l = 0; l < 128; l++) {
        float a = al[lp * 128 + l];
        float4 e4 = *(const float4*)(ep + (long long)l * HH);
        acc.x += a * e4.x; acc.y += a * e4.y; acc.z += a * e4.z; acc.w += a * e4.w;
    }
    *(float4*)(g_ctxp4 + ((long long)lp * BB + b) * HH + h) = acc;
}

// ---------------- stage concat(emb[tok], ctx) as bf16 hi/lo ----------------
__global__ void stage_xin_kernel(const float* __restrict__ emb) {
    int b = blockIdx.x;
    int e0 = threadIdx.x * 4;
    float v[4];
    if (e0 < EE) {
        float4 t = *(const float4*)(emb + (long long)g_tok[b] * EE + e0);
        v[0] = t.x; v[1] = t.y; v[2] = t.z; v[3] = t.w;
    } else {
        int h = e0 - EE;
#pragma unroll
        for (int j = 0; j < 4; j++) {
            v[j] = g_ctxp4[(long long)0 * BB * HH + b * HH + h + j]
                 + g_ctxp4[(long long)1 * BB * HH + b * HH + h + j]
                 + g_ctxp4[(long long)2 * BB * HH + b * HH + h + j]
                 + g_ctxp4[(long long)3 * BB * HH + b * HH + h + j];
        }
    }
    __nv_bfloat16 hh[4], ll[4];
#pragma unroll
    for (int j = 0; j < 4; j++) {
        hh[j] = __float2bfloat16(v[j]);
        ll[j] = __float2bfloat16(v[j] - __bfloat162float(hh[j]));
    }
    __nv_bfloat162 hp0; hp0.x = hh[0]; hp0.y = hh[1];
    __nv_bfloat162 hp1; hp1.x = hh[2]; hp1.y = hh[3];
    __nv_bfloat162 lp0; lp0.x = ll[0]; lp0.y = ll[1];
    __nv_bfloat162 lp1; lp1.x = ll[2]; lp1.y = ll[3];
    long long o = (long long)b * KX + e0;
    *(uint32_t*)(g_xinhi + o)     = *(uint32_t*)&hp0;
    *(uint32_t*)(g_xinhi + o + 2) = *(uint32_t*)&hp1;
    *(uint32_t*)(g_xinlo + o)     = *(uint32_t*)&lp0;
    *(uint32_t*)(g_xinlo + o + 2) = *(uint32_t*)&lp1;
}

// ---------------- combine x partials + bias -> bf16 hi/lo ----------------
__global__ void combine_x_kernel(const float* __restrict__ bin) {
    int b = blockIdx.x, n = threadIdx.x;
    float s = bin[n]
            + g_xp[0 * BB * EE + b * EE + n] + g_xp[1 * BB * EE + b * EE + n]
            + g_xp[2 * BB * EE + b * EE + n] + g_xp[3 * BB * EE + b * EE + n];
    __nv_bfloat16 hi = __float2bfloat16(s);
    g_xhi[b * EE + n] = hi;
    g_xlo[b * EE + n] = __float2bfloat16(s - __bfloat162float(hi));
}

// ---------------- LSTM elementwise cell update ----------------
__global__ void lstm_elt(int layer) {
    int id = blockIdx.x * blockDim.x + threadIdx.x;
    int b = id >> 10, hh = id & 1023;
    int o0 = b * G4H + hh;
    float gi = g_gp0[o0]        + g_gp1[o0]        + g_gp2[o0]        + g_gp3[o0];
    float gf = g_gp0[o0 + 1024] + g_gp1[o0 + 1024] + g_gp2[o0 + 1024] + g_gp3[o0 + 1024];
    float gg = g_gp0[o0 + 2048] + g_gp1[o0 + 2048] + g_gp2[o0 + 2048] + g_gp3[o0 + 2048];
    float go = g_gp0[o0 + 3072] + g_gp1[o0 + 3072] + g_gp2[o0 + 3072] + g_gp3[o0 + 3072];
    int hidx = layer * BB * HH + b * HH + hh;
    float cn = acc_sig(gf) * g_c[hidx] + acc_sig(gi) * tanhf(gg);
    g_c[hidx] = cn;
    float hn = acc_sig(go) * tanhf(cn);
    __nv_bfloat16 hb = __float2bfloat16(hn);
    g_hhi[hidx] = hb;
    g_hlo[hidx] = __float2bfloat16(hn - __bfloat162float(hb));
    if (layer == 1 && blockIdx.x == 0 && threadIdx.x < BB)
        g_amax[threadIdx.x] = 0ull;
}

// ---------------- finalize token ----------------
__global__ void tok_finalize(float* __restrict__ out, int t) {
    int b = threadIdx.x;
    if (b < BB) {
        unsigned long long p = g_amax[b];
        int idx = VV - (int)(unsigned int)(p & 0xFFFFFFFFu);
        g_tok[b] = idx;
        out[(long long)BB * TT * VV + b * TT + t] = (float)idx;
    }
}

// ---------------- launch ----------------
extern "C" void kernel_launch(void* const* d_in, const int* in_sizes, int n_in,
                              void* d_out, int out_size) {
    const float* enc_output = (const float*)d_in[0];
    const int*   trg        = (const int*)d_in[1];
    const float* emb        = (const float*)d_in[2];
    const float* W_att_enc  = (const float*)d_in[3];
    const float* b_att_enc  = (const float*)d_in[4];
    const float* W_att_dec  = (const float*)d_in[5];
    const float* b_att_dec  = (const float*)d_in[6];
    const float* v_att      = (const float*)d_in[7];
    const float* W_in       = (const float*)d_in[8];
    const float* b_in       = (const float*)d_in[9];
    const float* W_ih0      = (const float*)d_in[10];
    const float* W_hh0      = (const float*)d_in[11];
    const float* b_ih0      = (const float*)d_in[12];
    const float* b_hh0      = (const float*)d_in[13];
    const float* W_ih1      = (const float*)d_in[14];
    const float* W_hh1      = (const float*)d_in[15];
    const float* b_ih1      = (const float*)d_in[16];
    const float* b_hh1      = (const float*)d_in[17];
    const float* W_fc       = (const float*)d_in[18];
    const float* b_fc       = (const float*)d_in[19];
    float* out = (float*)d_out;

    init_kernel<<<(BB * VV + 255) / 256, 256>>>(trg, out);

    void *p1, *p2;
    auto packW = [&](const void* shi, const void* slo, const float* src, int N, int K) {
        cudaGetSymbolAddress(&p1, shi); cudaGetSymbolAddress(&p2, slo);
        long long words = (long long)N * K / 2;
        pack_w_kernel<<<(int)((words + 255) / 256), 256>>>(
            src, (__nv_bfloat16*)p1, (__nv_bfloat16*)p2, N, K);
    };
    packW(g_wenc_hi, g_wenc_lo, W_att_enc, HH, HH);
    packW(g_wdec_hi, g_wdec_lo, W_att_dec, HH, HH);
    packW(g_win_hi,  g_win_lo,  W_in,      EE, KX);
    packW(g_wih0_hi, g_wih0_lo, W_ih0,     G4H, EE);
    packW(g_whh0_hi, g_whh0_lo, W_hh0,     G4H, HH);
    packW(g_wih1_hi, g_wih1_lo, W_ih1,     G4H, HH);
    packW(g_whh1_hi, g_whh1_lo, W_hh1,     G4H, HH);
    packW(g_wfc_hi,  g_wfc_lo,  W_fc,      VV, HH);

    {   // linear split of enc_output (A operand of enc_proj GEMM)
        cudaGetSymbolAddress(&p1, g_ehi); cudaGetSymbolAddress(&p2, g_elo);
        long long n = (long long)BB * LL * HH / 4;
        split_w_kernel<<<(int)((n + 255) / 256), 256>>>(
            enc_output, (__nv_bfloat16*)p1, (__nv_bfloat16*)p2, (int)n);
    }

    gemm_encproj_mma<<<dim3(HH / 64, (BB * LL) / 32), 256>>>(b_att_enc);

    for (int t = 1; t < TT; t++) {
        gemm_q_mma<<<dim3(HH / 64, 4), 256>>>();
        energy_kernel<<<BB * (LL / 8), 256>>>(v_att, b_att_dec);
        ctx_part_kernel<<<dim3(2, 4, BB), 128>>>(enc_output);
        stage_xin_kernel<<<BB, KX / 4>>>(emb);
        gemm_x_mma<<<dim3(EE / 64, 4), 256>>>();
        combine_x_kernel<<<BB, EE>>>(b_in);

        gemm_gates_mma<<<256, 256>>>(0, b_ih0, b_hh0);
        lstm_elt<<<BB * HH / 256, 256>>>(0);

        gemm_gates_mma<<<256, 256>>>(1, b_ih1, b_hh1);
        lstm_elt<<<BB * HH / 256, 256>>>(1);

        gemm_fc_mma<<<VV / 64, 256>>>(b_fc, out + (long long)t * VV);
        tok_finalize<<<1, 32>>>(out, t);
    }
}